// round 3
// baseline (speedup 1.0000x reference)
#include <cuda_runtime.h>
#include <cuda_fp16.h>
#include <stdint.h>
#include <stddef.h>

// ---------------------------------------------------------------------------
// Problem constants
// ---------------------------------------------------------------------------
#define TOK   4096          // B*S tokens
#define DIN   4096
#define DOUT  4096
#define NE    8             // experts
#define RL    16            // lora rank
#define JD    128           // NE*RL
#define NEXTN (DOUT + JD)   // 4224 extended N (base cols + lora_A rows)

// ---------------------------------------------------------------------------
// Scratch (static device globals: allocation-free rule)
// ---------------------------------------------------------------------------
static __device__ __half g_xh [(size_t)TOK   * DIN];   // x in fp16
static __device__ __half g_wh [(size_t)NEXTN * DIN];   // [base_w ; lora_A] fp16
static __device__ __half g_bch[(size_t)DOUT  * JD];    // Bcat[o, e*16+r] fp16
static __device__ __half g_zh [(size_t)TOK   * JD];    // z = g*low fp16
static __device__ float  g_low[(size_t)TOK   * JD];    // low-rank activations
static __device__ float  g_gs [(size_t)TOK   * NE];    // routing weights * SCALING

// ---------------------------------------------------------------------------
// PTX helpers (base-ISA only: cp.async / ldmatrix / mma.sync)
// ---------------------------------------------------------------------------
__device__ __forceinline__ uint32_t smem_u32(const void* p) {
    uint32_t a;
    asm("{ .reg .u64 t; cvta.to.shared.u64 t, %1; cvt.u32.u64 %0, t; }"
        : "=r"(a) : "l"(p));
    return a;
}

__device__ __forceinline__ void ldsm_x4(uint32_t& r0, uint32_t& r1,
                                        uint32_t& r2, uint32_t& r3,
                                        uint32_t addr) {
    asm volatile("ldmatrix.sync.aligned.m8n8.x4.shared.b16 {%0,%1,%2,%3}, [%4];"
                 : "=r"(r0), "=r"(r1), "=r"(r2), "=r"(r3) : "r"(addr));
}

__device__ __forceinline__ void mma16816(float& c0, float& c1, float& c2, float& c3,
                                         uint32_t a0, uint32_t a1, uint32_t a2, uint32_t a3,
                                         uint32_t b0, uint32_t b1) {
    asm volatile(
        "mma.sync.aligned.m16n8k16.row.col.f32.f16.f16.f32 "
        "{%0,%1,%2,%3}, {%4,%5,%6,%7}, {%8,%9}, {%0,%1,%2,%3};"
        : "+f"(c0), "+f"(c1), "+f"(c2), "+f"(c3)
        : "r"(a0), "r"(a1), "r"(a2), "r"(a3), "r"(b0), "r"(b1));
}

#define CP_ASYNC16(smem, gptr)                                         \
    asm volatile("cp.async.cg.shared.global [%0], [%1], 16;"           \
                 :: "r"(smem), "l"(gptr))
#define CP_COMMIT() asm volatile("cp.async.commit_group;" ::: "memory")
#define CP_WAIT1()  asm volatile("cp.async.wait_group 1;" ::: "memory")
#define CP_WAIT0()  asm volatile("cp.async.wait_group 0;" ::: "memory")

// XOR swizzle for 128B rows (row bits 0-2 -> 16B-chunk bits 4-6)
__device__ __forceinline__ uint32_t sw128(uint32_t off) {
    return off ^ ((off >> 3) & 0x70);
}

// ---------------------------------------------------------------------------
// Conversion kernels (fp32 -> fp16 packing)
// ---------------------------------------------------------------------------
__global__ void __launch_bounds__(256) k_conv_x(const float4* __restrict__ x) {
    const int n4 = (TOK * DIN) / 4;
    for (int i = blockIdx.x * blockDim.x + threadIdx.x; i < n4;
         i += gridDim.x * blockDim.x) {
        float4 v = x[i];
        __half2* o = reinterpret_cast<__half2*>(g_xh + (size_t)i * 4);
        o[0] = __floats2half2_rn(v.x, v.y);
        o[1] = __floats2half2_rn(v.z, v.w);
    }
}

__global__ void __launch_bounds__(256) k_conv_w(const float4* __restrict__ bw,
                                                const float4* __restrict__ la) {
    const int n4_base = (DOUT * DIN) / 4;
    const int n4_tot  = (NEXTN * DIN) / 4;
    for (int i = blockIdx.x * blockDim.x + threadIdx.x; i < n4_tot;
         i += gridDim.x * blockDim.x) {
        float4 v = (i < n4_base) ? bw[i] : la[i - n4_base];
        __half2* o = reinterpret_cast<__half2*>(g_wh + (size_t)i * 4);
        o[0] = __floats2half2_rn(v.x, v.y);
        o[1] = __floats2half2_rn(v.z, v.w);
    }
}

// lora_B [E, DOUT, R] -> Bcat [DOUT, JD] with j = e*16 + r
__global__ void __launch_bounds__(256) k_conv_bc(const float* __restrict__ lb) {
    int idx = blockIdx.x * blockDim.x + threadIdx.x;
    if (idx < NE * DOUT * RL) {
        int e = idx >> 16;
        int rem = idx & 0xFFFF;
        int o = rem >> 4;
        int r = rem & 15;
        g_bch[(size_t)o * JD + e * RL + r] = __float2half(lb[idx]);
    }
}

// ---------------------------------------------------------------------------
// Gate: fp32 logits, exact top-2 + softmax, SCALING folded in
// ---------------------------------------------------------------------------
__global__ void __launch_bounds__(256) k_gate(const float* __restrict__ x,
                                              const float* __restrict__ gw) {
    int t = blockIdx.x;
    const float* xr = x + (size_t)t * DIN;
    float acc[NE];
#pragma unroll
    for (int e = 0; e < NE; e++) acc[e] = 0.f;
    for (int d = threadIdx.x; d < DIN; d += 256) {
        float xv = xr[d];
#pragma unroll
        for (int e = 0; e < NE; e++) acc[e] = fmaf(xv, gw[e * DIN + d], acc[e]);
    }
#pragma unroll
    for (int e = 0; e < NE; e++)
        for (int o = 16; o; o >>= 1)
            acc[e] += __shfl_xor_sync(0xffffffffu, acc[e], o);

    __shared__ float red[8][NE];
    int wid = threadIdx.x >> 5, lid = threadIdx.x & 31;
    if (lid == 0) {
#pragma unroll
        for (int e = 0; e < NE; e++) red[wid][e] = acc[e];
    }
    __syncthreads();
    if (threadIdx.x == 0) {
        float lg[NE];
#pragma unroll
        for (int e = 0; e < NE; e++) {
            float s = 0.f;
#pragma unroll
            for (int w = 0; w < 8; w++) s += red[w][e];
            lg[e] = s;
        }
        int i1 = 0;
        for (int e = 1; e < NE; e++) if (lg[e] > lg[i1]) i1 = e;
        int i2 = (i1 == 0) ? 1 : 0;
        for (int e = 0; e < NE; e++)
            if (e != i1 && lg[e] > lg[i2]) i2 = e;
        float e2 = expf(lg[i2] - lg[i1]);
        float inv = 1.f / (1.f + e2);
        float* o = g_gs + (size_t)t * NE;
#pragma unroll
        for (int e = 0; e < NE; e++) o[e] = 0.f;
        o[i1] = 2.0f * inv;        // SCALING = 2.0 folded
        o[i2] = 2.0f * e2 * inv;
    }
}

// z[t, j] = gs[t, e(j)] * low[t, j]   (fp16)
__global__ void __launch_bounds__(256) k_z() {
    int i = blockIdx.x * blockDim.x + threadIdx.x;
    if (i < TOK * JD) {
        int t = i >> 7, j = i & 127, e = j >> 4;
        g_zh[i] = __float2half(g_gs[t * NE + e] * g_low[i]);
    }
}

// ---------------------------------------------------------------------------
// mma.sync GEMM: D = A @ B^T, fp16 in / fp32 accum.
//   A: [Mtot, KTOT] K-contiguous   B: [Ntot, KTOT] K-contiguous
//   CTA tile 128x128xBK64, 256 thr (2x4 warps, warp tile 64x32),
//   2-stage cp.async double buffer, XOR-swizzled smem, ldmatrix frags.
//   MODE 0: A=g_xh, B=g_wh; epilogue col<DOUT -> out+bias else -> g_low
//   MODE 1: A=g_zh, B=g_bch; epilogue out += acc
// ---------------------------------------------------------------------------
#define BK 64
#define STAGE_BYTES (128 * BK * 2)          // 16 KB per operand per stage

template <int KTOT, int MODE>
__global__ void __launch_bounds__(256)
k_gemm(const float* __restrict__ bias, float* __restrict__ out) {
    extern __shared__ __align__(1024) char smem[];
    // layout: [A0 | A1 | B0 | B1], 16 KB each
    const uint32_t sbase = smem_u32(smem);

    const int tid = threadIdx.x;
    const int wid = tid >> 5, lane = tid & 31;
    const int warp_m = wid & 1;              // 2 warps over M (64 rows each)
    const int warp_n = wid >> 1;             // 4 warps over N (32 cols each)

    const __half* Abase = (MODE == 0) ? g_xh : g_zh;
    const __half* Bbase = (MODE == 0) ? g_wh : g_bch;

    // global load mapping: 8 threads per row (8 x 16B = 64 halves), 32 rows/pass, 4 passes
    const int ld_row = tid >> 3;             // 0..31
    const int ld_chk = tid & 7;              // 0..7 (16B chunk within row)
    const __half* gA = Abase + ((size_t)blockIdx.y * 128 + ld_row) * KTOT + ld_chk * 8;
    const __half* gB = Bbase + ((size_t)blockIdx.x * 128 + ld_row) * KTOT + ld_chk * 8;

    // smem store offsets (swizzled), one per pass
    uint32_t stA[4], stB[4];
#pragma unroll
    for (int p = 0; p < 4; p++) {
        uint32_t off = (uint32_t)(ld_row + 32 * p) * 128 + ld_chk * 16;
        stA[p] = sw128(off);
        stB[p] = sw128(off);
    }

    // ldmatrix source offsets
    const int aRow = warp_m * 64 + (lane & 15);         // + mi*16
    const int aCol = (lane >> 4) * 8;                   // halves, + ks*16
    const int bRow = warp_n * 32 + (lane & 7) + ((lane >> 4) * 8);  // + ni2*16
    const int bCol = ((lane >> 3) & 1) * 8;             // halves, + ks*16

    float acc[4][4][4];
#pragma unroll
    for (int mi = 0; mi < 4; mi++)
#pragma unroll
        for (int ni = 0; ni < 4; ni++)
#pragma unroll
            for (int c = 0; c < 4; c++) acc[mi][ni][c] = 0.f;

    const int NK = KTOT / BK;

    // prologue: stage 0
    {
        const __half* ga = gA;
        const __half* gb = gB;
#pragma unroll
        for (int p = 0; p < 4; p++) {
            CP_ASYNC16(sbase + stA[p],                 ga + (size_t)(32 * p) * KTOT);
            CP_ASYNC16(sbase + 2 * STAGE_BYTES + stB[p], gb + (size_t)(32 * p) * KTOT);
        }
        CP_COMMIT();
    }

    for (int kc = 0; kc < NK; kc++) {
        if (kc + 1 < NK) {
            const int st = (kc + 1) & 1;
            const __half* ga = gA + (kc + 1) * BK;
            const __half* gb = gB + (kc + 1) * BK;
#pragma unroll
            for (int p = 0; p < 4; p++) {
                CP_ASYNC16(sbase + st * STAGE_BYTES + stA[p],
                           ga + (size_t)(32 * p) * KTOT);
                CP_ASYNC16(sbase + (2 + st) * STAGE_BYTES + stB[p],
                           gb + (size_t)(32 * p) * KTOT);
            }
            CP_COMMIT();
            CP_WAIT1();
        } else {
            CP_WAIT0();
        }
        __syncthreads();

        const uint32_t aT = sbase + (kc & 1) * STAGE_BYTES;
        const uint32_t bT = sbase + (2 + (kc & 1)) * STAGE_BYTES;

#pragma unroll
        for (int ks = 0; ks < BK / 16; ks++) {
            uint32_t af[4][4];
#pragma unroll
            for (int mi = 0; mi < 4; mi++) {
                uint32_t off = (uint32_t)(aRow + mi * 16) * 128 +
                               (uint32_t)(aCol + ks * 16) * 2;
                ldsm_x4(af[mi][0], af[mi][1], af[mi][2], af[mi][3],
                        aT + sw128(off));
            }
            uint32_t bf[2][4];
#pragma unroll
            for (int ni2 = 0; ni2 < 2; ni2++) {
                uint32_t off = (uint32_t)(bRow + ni2 * 16) * 128 +
                               (uint32_t)(bCol + ks * 16) * 2;
                ldsm_x4(bf[ni2][0], bf[ni2][1], bf[ni2][2], bf[ni2][3],
                        bT + sw128(off));
            }
#pragma unroll
            for (int mi = 0; mi < 4; mi++) {
#pragma unroll
                for (int ni = 0; ni < 4; ni++) {
                    uint32_t b0 = bf[ni >> 1][(ni & 1) * 2 + 0];
                    uint32_t b1 = bf[ni >> 1][(ni & 1) * 2 + 1];
                    mma16816(acc[mi][ni][0], acc[mi][ni][1],
                             acc[mi][ni][2], acc[mi][ni][3],
                             af[mi][0], af[mi][1], af[mi][2], af[mi][3],
                             b0, b1);
                }
            }
        }
        __syncthreads();
    }

    // ---------------- epilogue ----------------
    const int colCta = blockIdx.x * 128;
    const int rowBase = blockIdx.y * 128 + warp_m * 64 + (lane >> 2);
    const int colBase = colCta + warp_n * 32 + (lane & 3) * 2;

    if (MODE == 0 && colCta >= DOUT) {
        // low-rank activation columns -> g_low [TOK, JD]
#pragma unroll
        for (int mi = 0; mi < 4; mi++) {
#pragma unroll
            for (int ni = 0; ni < 4; ni++) {
                int r0 = rowBase + mi * 16;
                int c0 = colBase + ni * 8 - DOUT;
                float* o = g_low + (size_t)r0 * JD + c0;
                o[0] = acc[mi][ni][0];
                o[1] = acc[mi][ni][1];
                o += 8 * JD;
                o[0] = acc[mi][ni][2];
                o[1] = acc[mi][ni][3];
            }
        }
    } else {
#pragma unroll
        for (int mi = 0; mi < 4; mi++) {
#pragma unroll
            for (int ni = 0; ni < 4; ni++) {
                int r0 = rowBase + mi * 16;
                int c0 = colBase + ni * 8;
                float* o = out + (size_t)r0 * DOUT + c0;
                if (MODE == 0) {
                    float b0 = __ldg(bias + c0);
                    float b1 = __ldg(bias + c0 + 1);
                    o[0] = acc[mi][ni][0] + b0;
                    o[1] = acc[mi][ni][1] + b1;
                    o += 8 * DOUT;
                    o[0] = acc[mi][ni][2] + b0;
                    o[1] = acc[mi][ni][3] + b1;
                } else {
                    o[0] += acc[mi][ni][0];
                    o[1] += acc[mi][ni][1];
                    o += 8 * DOUT;
                    o[0] += acc[mi][ni][2];
                    o[1] += acc[mi][ni][3];
                }
            }
        }
    }
}

// ---------------------------------------------------------------------------
// Launcher
// ---------------------------------------------------------------------------
extern "C" void kernel_launch(void* const* d_in, const int* in_sizes, int n_in,
                              void* d_out, int out_size) {
    const float* x      = (const float*)d_in[0];
    const float* gate_w = (const float*)d_in[1];
    const float* base_w = (const float*)d_in[2];
    const float* base_b = (const float*)d_in[3];
    const float* lora_A = (const float*)d_in[4];
    const float* lora_B = (const float*)d_in[5];
    float* out = (float*)d_out;

    const int smem_bytes = 4 * STAGE_BYTES;   // 64 KB
    cudaFuncSetAttribute(k_gemm<DIN, 0>,
                         cudaFuncAttributeMaxDynamicSharedMemorySize, smem_bytes);
    cudaFuncSetAttribute(k_gemm<JD, 1>,
                         cudaFuncAttributeMaxDynamicSharedMemorySize, smem_bytes);

    // pack fp16 operands
    k_conv_x<<<2048, 256>>>((const float4*)x);
    k_conv_w<<<2048, 256>>>((const float4*)base_w, (const float4*)lora_A);
    k_conv_bc<<<(NE * DOUT * RL + 255) / 256, 256>>>(lora_B);

    // fp32 gate (exact routing)
    k_gate<<<TOK, 256>>>(x, gate_w);

    // big GEMM: base output + bias, and low-rank activations (extended N)
    k_gemm<DIN, 0><<<dim3(NEXTN / 128, TOK / 128), 256, smem_bytes>>>(base_b, out);

    // routed, scaled low-rank activations
    k_z<<<(TOK * JD + 255) / 256, 256>>>();

    // out += z @ Bcat^T
    k_gemm<JD, 1><<<dim3(DOUT / 128, TOK / 128), 256, smem_bytes>>>(nullptr, out);
}

// round 4
// speedup vs baseline: 1.0192x; 1.0192x over previous
#include <cuda_runtime.h>
#include <cuda_fp16.h>
#include <stdint.h>
#include <stddef.h>

// ---------------------------------------------------------------------------
// Problem constants
// ---------------------------------------------------------------------------
#define TOK   4096          // B*S tokens
#define DIN   4096
#define DOUT  4096
#define NE    8             // experts
#define RL    16            // lora rank
#define JD    128           // NE*RL
#define NEXTN (DOUT + JD)   // 4224 extended N (base cols + lora_A rows)

// ---------------------------------------------------------------------------
// Scratch (static device globals: allocation-free rule)
// ---------------------------------------------------------------------------
static __device__ __half g_xh [(size_t)TOK   * DIN];   // x in fp16
static __device__ __half g_wh [(size_t)NEXTN * DIN];   // [base_w ; lora_A] fp16
static __device__ __half g_bch[(size_t)DOUT  * JD];    // Bcat[o, e*16+r] fp16
static __device__ __half g_zh [(size_t)TOK   * JD];    // z = g*low fp16
static __device__ float  g_low[(size_t)TOK   * JD];    // low-rank activations
static __device__ float  g_gs [(size_t)TOK   * NE];    // routing weights * SCALING

// ---------------------------------------------------------------------------
// PTX helpers
// ---------------------------------------------------------------------------
__device__ __forceinline__ uint32_t smem_u32(const void* p) {
    uint32_t a;
    asm("{ .reg .u64 t; cvta.to.shared.u64 t, %1; cvt.u32.u64 %0, t; }"
        : "=r"(a) : "l"(p));
    return a;
}

__device__ __forceinline__ void ldsm_x4(uint32_t& r0, uint32_t& r1,
                                        uint32_t& r2, uint32_t& r3,
                                        uint32_t addr) {
    asm volatile("ldmatrix.sync.aligned.m8n8.x4.shared.b16 {%0,%1,%2,%3}, [%4];"
                 : "=r"(r0), "=r"(r1), "=r"(r2), "=r"(r3) : "r"(addr));
}

__device__ __forceinline__ void mma16816(float& c0, float& c1, float& c2, float& c3,
                                         uint32_t a0, uint32_t a1, uint32_t a2, uint32_t a3,
                                         uint32_t b0, uint32_t b1) {
    asm volatile(
        "mma.sync.aligned.m16n8k16.row.col.f32.f16.f16.f32 "
        "{%0,%1,%2,%3}, {%4,%5,%6,%7}, {%8,%9}, {%0,%1,%2,%3};"
        : "+f"(c0), "+f"(c1), "+f"(c2), "+f"(c3)
        : "r"(a0), "r"(a1), "r"(a2), "r"(a3), "r"(b0), "r"(b1));
}

#define CP_ASYNC16(smem, gptr)                                         \
    asm volatile("cp.async.cg.shared.global [%0], [%1], 16;"           \
                 :: "r"(smem), "l"(gptr))
#define CP_COMMIT() asm volatile("cp.async.commit_group;" ::: "memory")
#define CP_WAIT1()  asm volatile("cp.async.wait_group 1;" ::: "memory")

// XOR swizzle for 128B rows
__device__ __forceinline__ uint32_t sw128(uint32_t off) {
    return off ^ ((off >> 3) & 0x70);
}

// ---------------------------------------------------------------------------
// Conversion kernels
// ---------------------------------------------------------------------------
__global__ void __launch_bounds__(256) k_conv_w(const float4* __restrict__ bw,
                                                const float4* __restrict__ la) {
    const int n4_base = (DOUT * DIN) / 4;
    const int n4_tot  = (NEXTN * DIN) / 4;
    for (int i = blockIdx.x * blockDim.x + threadIdx.x; i < n4_tot;
         i += gridDim.x * blockDim.x) {
        float4 v = (i < n4_base) ? bw[i] : la[i - n4_base];
        __half2* o = reinterpret_cast<__half2*>(g_wh + (size_t)i * 4);
        o[0] = __floats2half2_rn(v.x, v.y);
        o[1] = __floats2half2_rn(v.z, v.w);
    }
}

// lora_B [E, DOUT, R] -> Bcat [DOUT, JD] with j = e*16 + r
__global__ void __launch_bounds__(256) k_conv_bc(const float* __restrict__ lb) {
    int idx = blockIdx.x * blockDim.x + threadIdx.x;
    if (idx < NE * DOUT * RL) {
        int e = idx >> 16;
        int rem = idx & 0xFFFF;
        int o = rem >> 4;
        int r = rem & 15;
        g_bch[(size_t)o * JD + e * RL + r] = __float2half(lb[idx]);
    }
}

// ---------------------------------------------------------------------------
// Gate (fused with x fp32->fp16 conversion).
//   256 blocks x 256 threads; block handles 16 tokens (2 per warp).
//   gate_w staged through smem in 512-col chunks (16 KB) -> gw L2 traffic
//   drops from 512 MB to 32 MB. x streamed once; fp16 copy emitted inline.
//   fp32 logits, exact top-2 + softmax, SCALING folded in.
// ---------------------------------------------------------------------------
__global__ void __launch_bounds__(256) k_gate(const float* __restrict__ x,
                                              const float* __restrict__ gw) {
    __shared__ float4 sgw[NE * 128];      // 8 x 512 floats = 16 KB
    const int tid = threadIdx.x;
    const int wid = tid >> 5, lane = tid & 31;
    const int t0 = blockIdx.x * 16 + wid * 2;

    float acc[2][NE];
#pragma unroll
    for (int tt = 0; tt < 2; tt++)
#pragma unroll
        for (int e = 0; e < NE; e++) acc[tt][e] = 0.f;

    for (int ch = 0; ch < DIN / 512; ch++) {
        // stage gw[:, ch*512 .. +512) into smem
#pragma unroll
        for (int i = tid; i < NE * 128; i += 256) {
            int e = i >> 7, c = i & 127;
            sgw[i] = reinterpret_cast<const float4*>(gw + (size_t)e * DIN + ch * 512)[c];
        }
        __syncthreads();
#pragma unroll
        for (int tt = 0; tt < 2; tt++) {
            const float4* xr = reinterpret_cast<const float4*>(
                x + (size_t)(t0 + tt) * DIN + ch * 512);
            __half2* xo = reinterpret_cast<__half2*>(
                g_xh + (size_t)(t0 + tt) * DIN + ch * 512);
#pragma unroll
            for (int j0 = 0; j0 < 4; j0++) {
                int j = lane + j0 * 32;
                float4 v = xr[j];
                xo[2 * j]     = __floats2half2_rn(v.x, v.y);
                xo[2 * j + 1] = __floats2half2_rn(v.z, v.w);
#pragma unroll
                for (int e = 0; e < NE; e++) {
                    float4 w = sgw[e * 128 + j];
                    acc[tt][e] = fmaf(v.x, w.x,
                                 fmaf(v.y, w.y,
                                 fmaf(v.z, w.z,
                                 fmaf(v.w, w.w, acc[tt][e]))));
                }
            }
        }
        __syncthreads();
    }

    // reduce across lanes
#pragma unroll
    for (int tt = 0; tt < 2; tt++)
#pragma unroll
        for (int e = 0; e < NE; e++)
            for (int o = 16; o; o >>= 1)
                acc[tt][e] += __shfl_xor_sync(0xffffffffu, acc[tt][e], o);

    if (lane == 0) {
#pragma unroll
        for (int tt = 0; tt < 2; tt++) {
            float* lg = acc[tt];
            int i1 = 0;
            for (int e = 1; e < NE; e++) if (lg[e] > lg[i1]) i1 = e;
            int i2 = (i1 == 0) ? 1 : 0;
            for (int e = 0; e < NE; e++)
                if (e != i1 && lg[e] > lg[i2]) i2 = e;
            float e2 = expf(lg[i2] - lg[i1]);
            float inv = 1.f / (1.f + e2);
            float* o = g_gs + (size_t)(t0 + tt) * NE;
#pragma unroll
            for (int e = 0; e < NE; e++) o[e] = 0.f;
            o[i1] = 2.0f * inv;        // SCALING = 2.0 folded
            o[i2] = 2.0f * e2 * inv;
        }
    }
}

// z[t, j] = gs[t, e(j)] * low[t, j]   (fp16)
__global__ void __launch_bounds__(256) k_z() {
    int i = blockIdx.x * blockDim.x + threadIdx.x;
    if (i < TOK * JD) {
        int t = i >> 7, j = i & 127, e = j >> 4;
        g_zh[i] = __float2half(g_gs[t * NE + e] * g_low[i]);
    }
}

// ---------------------------------------------------------------------------
// mma.sync GEMM: D = A @ B^T, fp16 in / fp32 accum.
//   CTA tile 256(M) x 128(N) x BK64, 256 thr = 4(M)x2(N) warps (64x64/warp),
//   3-stage cp.async pipeline, one __syncthreads per K-chunk.
//   MODE 0: A=g_xh, B=g_wh; epilogue col<DOUT -> out+bias else -> g_low
//   MODE 1: A=g_zh, B=g_bch; epilogue out += acc
// ---------------------------------------------------------------------------
#define BK 64
#define A_STAGE (256 * BK * 2)   // 32 KB
#define B_STAGE (128 * BK * 2)   // 16 KB
#define B_OFF   (3 * A_STAGE)    // B stages after the 3 A stages
#define SMEM_TOTAL (3 * (A_STAGE + B_STAGE))   // 144 KB

template <int KTOT, int MODE>
__global__ void __launch_bounds__(256)
k_gemm(const float* __restrict__ bias, float* __restrict__ out) {
    extern __shared__ __align__(1024) char smem[];
    const uint32_t sbase = smem_u32(smem);

    const int tid = threadIdx.x;
    const int wid = tid >> 5, lane = tid & 31;
    const int warp_m = wid & 3;              // 4 warps over M (64 rows each)
    const int warp_n = wid >> 2;             // 2 warps over N (64 cols each)

    const __half* Abase = (MODE == 0) ? g_xh : g_zh;
    const __half* Bbase = (MODE == 0) ? g_wh : g_bch;

    // global load mapping: 8 threads/row (8 x 16B = 64 halves), 32 rows/pass
    const int ld_row = tid >> 3;             // 0..31
    const int ld_chk = tid & 7;              // 0..7
    const __half* gA = Abase + ((size_t)blockIdx.y * 256 + ld_row) * KTOT + ld_chk * 8;
    const __half* gB = Bbase + ((size_t)blockIdx.x * 128 + ld_row) * KTOT + ld_chk * 8;

    uint32_t stOff[8];
#pragma unroll
    for (int p = 0; p < 8; p++)
        stOff[p] = sw128((uint32_t)(ld_row + 32 * p) * 128 + ld_chk * 16);

    // ldmatrix source coordinates
    const int aRow = warp_m * 64 + (lane & 15);                      // + mi*16
    const int aColH = (lane >> 4) * 8;                               // + ks*16 (halves)
    const int bRow = warp_n * 64 + (lane & 7) + ((lane >> 4) * 8);   // + nj*16
    const int bColH = ((lane >> 3) & 1) * 8;                         // + ks*16 (halves)

    float acc[4][8][4];
#pragma unroll
    for (int mi = 0; mi < 4; mi++)
#pragma unroll
        for (int ni = 0; ni < 8; ni++)
#pragma unroll
            for (int c = 0; c < 4; c++) acc[mi][ni][c] = 0.f;

    const int NK = KTOT / BK;

    // stage issue helper (kstage assumed < NK)
    auto issue = [&](int kstage) {
        const int st = kstage % 3;
        const __half* ga = gA + kstage * BK;
        const __half* gb = gB + kstage * BK;
        const uint32_t aBuf = sbase + st * A_STAGE;
        const uint32_t bBuf = sbase + B_OFF + st * B_STAGE;
#pragma unroll
        for (int p = 0; p < 8; p++)
            CP_ASYNC16(aBuf + stOff[p], ga + (size_t)(32 * p) * KTOT);
#pragma unroll
        for (int p = 0; p < 4; p++)
            CP_ASYNC16(bBuf + stOff[p], gb + (size_t)(32 * p) * KTOT);
    };

    // prologue: stages 0, 1 (NK >= 2 always)
    issue(0); CP_COMMIT();
    issue(1); CP_COMMIT();

    for (int kc = 0; kc < NK; kc++) {
        CP_WAIT1();            // stage kc resident (this thread's part)
        __syncthreads();       // all threads' parts visible

        // refill: stage kc+2 goes into buffer (kc+2)%3 == (kc-1)%3,
        // whose compute finished before this barrier.
        if (kc + 2 < NK) issue(kc + 2);
        CP_COMMIT();           // always commit (possibly empty) to keep counts aligned

        const uint32_t aT = sbase + (kc % 3) * A_STAGE;
        const uint32_t bT = sbase + B_OFF + (kc % 3) * B_STAGE;

#pragma unroll
        for (int ks = 0; ks < BK / 16; ks++) {
            uint32_t af[4][4];
#pragma unroll
            for (int mi = 0; mi < 4; mi++) {
                uint32_t off = (uint32_t)(aRow + mi * 16) * 128 +
                               (uint32_t)(aColH + ks * 16) * 2;
                ldsm_x4(af[mi][0], af[mi][1], af[mi][2], af[mi][3],
                        aT + sw128(off));
            }
            uint32_t bf[4][4];
#pragma unroll
            for (int nj = 0; nj < 4; nj++) {
                uint32_t off = (uint32_t)(bRow + nj * 16) * 128 +
                               (uint32_t)(bColH + ks * 16) * 2;
                ldsm_x4(bf[nj][0], bf[nj][1], bf[nj][2], bf[nj][3],
                        bT + sw128(off));
            }
#pragma unroll
            for (int mi = 0; mi < 4; mi++) {
#pragma unroll
                for (int ni = 0; ni < 8; ni++) {
                    uint32_t b0 = bf[ni >> 1][(ni & 1) * 2 + 0];
                    uint32_t b1 = bf[ni >> 1][(ni & 1) * 2 + 1];
                    mma16816(acc[mi][ni][0], acc[mi][ni][1],
                             acc[mi][ni][2], acc[mi][ni][3],
                             af[mi][0], af[mi][1], af[mi][2], af[mi][3],
                             b0, b1);
                }
            }
        }
        __syncthreads();       // everyone done reading buffer kc%3
    }

    // ---------------- epilogue ----------------
    const int colCta  = blockIdx.x * 128;
    const int rowBase = blockIdx.y * 256 + warp_m * 64 + (lane >> 2);
    const int colBase = colCta + warp_n * 64 + (lane & 3) * 2;

    if (MODE == 0 && colCta >= DOUT) {
#pragma unroll
        for (int mi = 0; mi < 4; mi++) {
#pragma unroll
            for (int ni = 0; ni < 8; ni++) {
                int r0 = rowBase + mi * 16;
                int c0 = colBase + ni * 8 - DOUT;
                float* o = g_low + (size_t)r0 * JD + c0;
                o[0] = acc[mi][ni][0];
                o[1] = acc[mi][ni][1];
                o += 8 * JD;
                o[0] = acc[mi][ni][2];
                o[1] = acc[mi][ni][3];
            }
        }
    } else {
#pragma unroll
        for (int mi = 0; mi < 4; mi++) {
#pragma unroll
            for (int ni = 0; ni < 8; ni++) {
                int r0 = rowBase + mi * 16;
                int c0 = colBase + ni * 8;
                float* o = out + (size_t)r0 * DOUT + c0;
                if (MODE == 0) {
                    float b0 = __ldg(bias + c0);
                    float b1 = __ldg(bias + c0 + 1);
                    o[0] = acc[mi][ni][0] + b0;
                    o[1] = acc[mi][ni][1] + b1;
                    o += 8 * DOUT;
                    o[0] = acc[mi][ni][2] + b0;
                    o[1] = acc[mi][ni][3] + b1;
                } else {
                    o[0] += acc[mi][ni][0];
                    o[1] += acc[mi][ni][1];
                    o += 8 * DOUT;
                    o[0] += acc[mi][ni][2];
                    o[1] += acc[mi][ni][3];
                }
            }
        }
    }
}

// ---------------------------------------------------------------------------
// Launcher
// ---------------------------------------------------------------------------
extern "C" void kernel_launch(void* const* d_in, const int* in_sizes, int n_in,
                              void* d_out, int out_size) {
    const float* x      = (const float*)d_in[0];
    const float* gate_w = (const float*)d_in[1];
    const float* base_w = (const float*)d_in[2];
    const float* base_b = (const float*)d_in[3];
    const float* lora_A = (const float*)d_in[4];
    const float* lora_B = (const float*)d_in[5];
    float* out = (float*)d_out;

    cudaFuncSetAttribute(k_gemm<DIN, 0>,
                         cudaFuncAttributeMaxDynamicSharedMemorySize, SMEM_TOTAL);
    cudaFuncSetAttribute(k_gemm<JD, 1>,
                         cudaFuncAttributeMaxDynamicSharedMemorySize, SMEM_TOTAL);

    // pack fp16 weights
    k_conv_w<<<2048, 256>>>((const float4*)base_w, (const float4*)lora_A);
    k_conv_bc<<<(NE * DOUT * RL + 255) / 256, 256>>>(lora_B);

    // fp32 gate (exact routing) + fused x -> fp16 conversion
    k_gate<<<TOK / 16, 256>>>(x, gate_w);

    // big GEMM: base output + bias, and low-rank activations (extended N)
    k_gemm<DIN, 0><<<dim3(NEXTN / 128, TOK / 256), 256, SMEM_TOTAL>>>(base_b, out);

    // routed, scaled low-rank activations
    k_z<<<(TOK * JD + 255) / 256, 256>>>();

    // out += z @ Bcat^T
    k_gemm<JD, 1><<<dim3(DOUT / 128, TOK / 256), 256, SMEM_TOTAL>>>(nullptr, out);
}

// round 5
// speedup vs baseline: 1.0634x; 1.0434x over previous
#include <cuda_runtime.h>
#include <cuda_fp16.h>
#include <stdint.h>
#include <stddef.h>

// ---------------------------------------------------------------------------
// Problem constants
// ---------------------------------------------------------------------------
#define TOK   4096          // B*S tokens
#define DIN   4096
#define DOUT  4096
#define NE    8             // experts
#define RL    16            // lora rank
#define JD    128           // NE*RL
#define NEXTN (DOUT + JD)   // 4224 extended N (base cols + lora_A rows)

// ---------------------------------------------------------------------------
// Scratch (static device globals: allocation-free rule)
// ---------------------------------------------------------------------------
static __device__ __half g_xh [(size_t)TOK   * DIN];   // x in fp16
static __device__ __half g_wh [(size_t)NEXTN * DIN];   // [base_w ; lora_A] fp16
static __device__ __half g_bch[(size_t)DOUT  * JD];    // Bcat[o, e*16+r] fp16
static __device__ __half g_zh [(size_t)TOK   * JD];    // z = g*low fp16
static __device__ float  g_low[(size_t)TOK   * JD];    // low-rank activations
static __device__ float  g_gs [(size_t)TOK   * NE];    // routing weights * SCALING

// ---------------------------------------------------------------------------
// PTX helpers
// ---------------------------------------------------------------------------
__device__ __forceinline__ uint32_t smem_u32(const void* p) {
    uint32_t a;
    asm("{ .reg .u64 t; cvta.to.shared.u64 t, %1; cvt.u32.u64 %0, t; }"
        : "=r"(a) : "l"(p));
    return a;
}

__device__ __forceinline__ void ldsm_x4(uint32_t& r0, uint32_t& r1,
                                        uint32_t& r2, uint32_t& r3,
                                        uint32_t addr) {
    asm volatile("ldmatrix.sync.aligned.m8n8.x4.shared.b16 {%0,%1,%2,%3}, [%4];"
                 : "=r"(r0), "=r"(r1), "=r"(r2), "=r"(r3) : "r"(addr));
}

__device__ __forceinline__ void mma16816(float& c0, float& c1, float& c2, float& c3,
                                         uint32_t a0, uint32_t a1, uint32_t a2, uint32_t a3,
                                         uint32_t b0, uint32_t b1) {
    asm volatile(
        "mma.sync.aligned.m16n8k16.row.col.f32.f16.f16.f32 "
        "{%0,%1,%2,%3}, {%4,%5,%6,%7}, {%8,%9}, {%0,%1,%2,%3};"
        : "+f"(c0), "+f"(c1), "+f"(c2), "+f"(c3)
        : "r"(a0), "r"(a1), "r"(a2), "r"(a3), "r"(b0), "r"(b1));
}

#define CP_ASYNC16(smem, gptr)                                         \
    asm volatile("cp.async.cg.shared.global [%0], [%1], 16;"           \
                 :: "r"(smem), "l"(gptr))
#define CP_COMMIT() asm volatile("cp.async.commit_group;" ::: "memory")
#define CP_WAIT2()  asm volatile("cp.async.wait_group 2;" ::: "memory")

// XOR swizzle for 128B rows
__device__ __forceinline__ uint32_t sw128(uint32_t off) {
    return off ^ ((off >> 3) & 0x70);
}

// ---------------------------------------------------------------------------
// Conversion kernels
// ---------------------------------------------------------------------------
__global__ void __launch_bounds__(256) k_conv_w(const float4* __restrict__ bw,
                                                const float4* __restrict__ la) {
    const int n4_base = (DOUT * DIN) / 4;
    const int n4_tot  = (NEXTN * DIN) / 4;
    for (int i = blockIdx.x * blockDim.x + threadIdx.x; i < n4_tot;
         i += gridDim.x * blockDim.x) {
        float4 v = (i < n4_base) ? bw[i] : la[i - n4_base];
        __half2* o = reinterpret_cast<__half2*>(g_wh + (size_t)i * 4);
        o[0] = __floats2half2_rn(v.x, v.y);
        o[1] = __floats2half2_rn(v.z, v.w);
    }
}

// lora_B [E, DOUT, R] -> Bcat [DOUT, JD] with j = e*16 + r
__global__ void __launch_bounds__(256) k_conv_bc(const float* __restrict__ lb) {
    int idx = blockIdx.x * blockDim.x + threadIdx.x;
    if (idx < NE * DOUT * RL) {
        int e = idx >> 16;
        int rem = idx & 0xFFFF;
        int o = rem >> 4;
        int r = rem & 15;
        g_bch[(size_t)o * JD + e * RL + r] = __float2half(lb[idx]);
    }
}

// ---------------------------------------------------------------------------
// Gate (fused with x fp32->fp16 conversion). See R4 notes.
// ---------------------------------------------------------------------------
__global__ void __launch_bounds__(256) k_gate(const float* __restrict__ x,
                                              const float* __restrict__ gw) {
    __shared__ float4 sgw[NE * 128];      // 8 x 512 floats = 16 KB
    const int tid = threadIdx.x;
    const int wid = tid >> 5, lane = tid & 31;
    const int t0 = blockIdx.x * 16 + wid * 2;

    float acc[2][NE];
#pragma unroll
    for (int tt = 0; tt < 2; tt++)
#pragma unroll
        for (int e = 0; e < NE; e++) acc[tt][e] = 0.f;

    for (int ch = 0; ch < DIN / 512; ch++) {
#pragma unroll
        for (int i = tid; i < NE * 128; i += 256) {
            int e = i >> 7, c = i & 127;
            sgw[i] = reinterpret_cast<const float4*>(gw + (size_t)e * DIN + ch * 512)[c];
        }
        __syncthreads();
#pragma unroll
        for (int tt = 0; tt < 2; tt++) {
            const float4* xr = reinterpret_cast<const float4*>(
                x + (size_t)(t0 + tt) * DIN + ch * 512);
            __half2* xo = reinterpret_cast<__half2*>(
                g_xh + (size_t)(t0 + tt) * DIN + ch * 512);
#pragma unroll
            for (int j0 = 0; j0 < 4; j0++) {
                int j = lane + j0 * 32;
                float4 v = xr[j];
                xo[2 * j]     = __floats2half2_rn(v.x, v.y);
                xo[2 * j + 1] = __floats2half2_rn(v.z, v.w);
#pragma unroll
                for (int e = 0; e < NE; e++) {
                    float4 w = sgw[e * 128 + j];
                    acc[tt][e] = fmaf(v.x, w.x,
                                 fmaf(v.y, w.y,
                                 fmaf(v.z, w.z,
                                 fmaf(v.w, w.w, acc[tt][e]))));
                }
            }
        }
        __syncthreads();
    }

#pragma unroll
    for (int tt = 0; tt < 2; tt++)
#pragma unroll
        for (int e = 0; e < NE; e++)
            for (int o = 16; o; o >>= 1)
                acc[tt][e] += __shfl_xor_sync(0xffffffffu, acc[tt][e], o);

    if (lane == 0) {
#pragma unroll
        for (int tt = 0; tt < 2; tt++) {
            float* lg = acc[tt];
            int i1 = 0;
            for (int e = 1; e < NE; e++) if (lg[e] > lg[i1]) i1 = e;
            int i2 = (i1 == 0) ? 1 : 0;
            for (int e = 0; e < NE; e++)
                if (e != i1 && lg[e] > lg[i2]) i2 = e;
            float e2 = expf(lg[i2] - lg[i1]);
            float inv = 1.f / (1.f + e2);
            float* o = g_gs + (size_t)(t0 + tt) * NE;
#pragma unroll
            for (int e = 0; e < NE; e++) o[e] = 0.f;
            o[i1] = 2.0f * inv;        // SCALING = 2.0 folded
            o[i2] = 2.0f * e2 * inv;
        }
    }
}

// z[t, j] = gs[t, e(j)] * low[t, j]   (fp16)
__global__ void __launch_bounds__(256) k_z() {
    int i = blockIdx.x * blockDim.x + threadIdx.x;
    if (i < TOK * JD) {
        int t = i >> 7, j = i & 127, e = j >> 4;
        g_zh[i] = __float2half(g_gs[t * NE + e] * g_low[i]);
    }
}

// ---------------------------------------------------------------------------
// mma.sync GEMM: D = A @ B^T, fp16 in / fp32 accum.
//   CTA tile 256(M) x 128(N) x BK64, 256 thr = 4(M)x2(N) warps (64x64/warp),
//   4-stage cp.async pipeline, ONE __syncthreads per K-chunk:
//     wait_group 2 -> barrier -> issue(kc+3) -> compute(kc)
//   RAW: own-group wait before barrier; WAR: buffer (kc+3)%4 == (kc-1)%4 was
//   fully read before this barrier.
// ---------------------------------------------------------------------------
#define BK 64
#define NSTAGE 4
#define A_STAGE (256 * BK * 2)   // 32 KB
#define B_STAGE (128 * BK * 2)   // 16 KB
#define B_OFF   (NSTAGE * A_STAGE)
#define SMEM_TOTAL (NSTAGE * (A_STAGE + B_STAGE))   // 192 KB

template <int KTOT, int MODE>
__global__ void __launch_bounds__(256)
k_gemm(const float* __restrict__ bias, float* __restrict__ out) {
    extern __shared__ __align__(1024) char smem[];
    const uint32_t sbase = smem_u32(smem);

    const int tid = threadIdx.x;
    const int wid = tid >> 5, lane = tid & 31;
    const int warp_m = wid & 3;              // 4 warps over M (64 rows each)
    const int warp_n = wid >> 2;             // 2 warps over N (64 cols each)

    const __half* Abase = (MODE == 0) ? g_xh : g_zh;
    const __half* Bbase = (MODE == 0) ? g_wh : g_bch;

    const int ld_row = tid >> 3;             // 0..31
    const int ld_chk = tid & 7;              // 0..7
    const __half* gA = Abase + ((size_t)blockIdx.y * 256 + ld_row) * KTOT + ld_chk * 8;
    const __half* gB = Bbase + ((size_t)blockIdx.x * 128 + ld_row) * KTOT + ld_chk * 8;

    uint32_t stOff[8];
#pragma unroll
    for (int p = 0; p < 8; p++)
        stOff[p] = sw128((uint32_t)(ld_row + 32 * p) * 128 + ld_chk * 16);

    const int aRow = warp_m * 64 + (lane & 15);
    const int aColH = (lane >> 4) * 8;
    const int bRow = warp_n * 64 + (lane & 7) + ((lane >> 4) * 8);
    const int bColH = ((lane >> 3) & 1) * 8;

    float acc[4][8][4];
#pragma unroll
    for (int mi = 0; mi < 4; mi++)
#pragma unroll
        for (int ni = 0; ni < 8; ni++)
#pragma unroll
            for (int c = 0; c < 4; c++) acc[mi][ni][c] = 0.f;

    const int NK = KTOT / BK;

    auto issue = [&](int kstage) {
        const int st = kstage % NSTAGE;
        const __half* ga = gA + kstage * BK;
        const __half* gb = gB + kstage * BK;
        const uint32_t aBuf = sbase + st * A_STAGE;
        const uint32_t bBuf = sbase + B_OFF + st * B_STAGE;
#pragma unroll
        for (int p = 0; p < 8; p++)
            CP_ASYNC16(aBuf + stOff[p], ga + (size_t)(32 * p) * KTOT);
#pragma unroll
        for (int p = 0; p < 4; p++)
            CP_ASYNC16(bBuf + stOff[p], gb + (size_t)(32 * p) * KTOT);
    };

    // prologue: stages 0..2 (guarded for small NK); always 3 commits
#pragma unroll
    for (int s = 0; s < 3; s++) {
        if (s < NK) issue(s);
        CP_COMMIT();
    }

    for (int kc = 0; kc < NK; kc++) {
        CP_WAIT2();            // own groups: stage kc data written
        __syncthreads();       // visibility to all; WAR protection below

        if (kc + 3 < NK) issue(kc + 3);
        CP_COMMIT();           // one group per iteration (possibly empty)

        const uint32_t aT = sbase + (kc % NSTAGE) * A_STAGE;
        const uint32_t bT = sbase + B_OFF + (kc % NSTAGE) * B_STAGE;

#pragma unroll
        for (int ks = 0; ks < BK / 16; ks++) {
            uint32_t af[4][4];
#pragma unroll
            for (int mi = 0; mi < 4; mi++) {
                uint32_t off = (uint32_t)(aRow + mi * 16) * 128 +
                               (uint32_t)(aColH + ks * 16) * 2;
                ldsm_x4(af[mi][0], af[mi][1], af[mi][2], af[mi][3],
                        aT + sw128(off));
            }
            uint32_t bf[4][4];
#pragma unroll
            for (int nj = 0; nj < 4; nj++) {
                uint32_t off = (uint32_t)(bRow + nj * 16) * 128 +
                               (uint32_t)(bColH + ks * 16) * 2;
                ldsm_x4(bf[nj][0], bf[nj][1], bf[nj][2], bf[nj][3],
                        bT + sw128(off));
            }
#pragma unroll
            for (int mi = 0; mi < 4; mi++) {
#pragma unroll
                for (int ni = 0; ni < 8; ni++) {
                    uint32_t b0 = bf[ni >> 1][(ni & 1) * 2 + 0];
                    uint32_t b1 = bf[ni >> 1][(ni & 1) * 2 + 1];
                    mma16816(acc[mi][ni][0], acc[mi][ni][1],
                             acc[mi][ni][2], acc[mi][ni][3],
                             af[mi][0], af[mi][1], af[mi][2], af[mi][3],
                             b0, b1);
                }
            }
        }
        // no trailing barrier: next iteration's barrier provides WAR safety
    }

    // ---------------- epilogue ----------------
    const int colCta  = blockIdx.x * 128;
    const int rowBase = blockIdx.y * 256 + warp_m * 64 + (lane >> 2);
    const int colBase = colCta + warp_n * 64 + (lane & 3) * 2;

    if (MODE == 0 && colCta >= DOUT) {
#pragma unroll
        for (int mi = 0; mi < 4; mi++) {
#pragma unroll
            for (int ni = 0; ni < 8; ni++) {
                int r0 = rowBase + mi * 16;
                int c0 = colBase + ni * 8 - DOUT;
                float* o = g_low + (size_t)r0 * JD + c0;
                o[0] = acc[mi][ni][0];
                o[1] = acc[mi][ni][1];
                o += 8 * JD;
                o[0] = acc[mi][ni][2];
                o[1] = acc[mi][ni][3];
            }
        }
    } else {
#pragma unroll
        for (int mi = 0; mi < 4; mi++) {
#pragma unroll
            for (int ni = 0; ni < 8; ni++) {
                int r0 = rowBase + mi * 16;
                int c0 = colBase + ni * 8;
                float* o = out + (size_t)r0 * DOUT + c0;
                if (MODE == 0) {
                    float b0 = __ldg(bias + c0);
                    float b1 = __ldg(bias + c0 + 1);
                    o[0] = acc[mi][ni][0] + b0;
                    o[1] = acc[mi][ni][1] + b1;
                    o += 8 * DOUT;
                    o[0] = acc[mi][ni][2] + b0;
                    o[1] = acc[mi][ni][3] + b1;
                } else {
                    o[0] += acc[mi][ni][0];
                    o[1] += acc[mi][ni][1];
                    o += 8 * DOUT;
                    o[0] += acc[mi][ni][2];
                    o[1] += acc[mi][ni][3];
                }
            }
        }
    }
}

// ---------------------------------------------------------------------------
// Launcher
// ---------------------------------------------------------------------------
extern "C" void kernel_launch(void* const* d_in, const int* in_sizes, int n_in,
                              void* d_out, int out_size) {
    const float* x      = (const float*)d_in[0];
    const float* gate_w = (const float*)d_in[1];
    const float* base_w = (const float*)d_in[2];
    const float* base_b = (const float*)d_in[3];
    const float* lora_A = (const float*)d_in[4];
    const float* lora_B = (const float*)d_in[5];
    float* out = (float*)d_out;

    cudaFuncSetAttribute(k_gemm<DIN, 0>,
                         cudaFuncAttributeMaxDynamicSharedMemorySize, SMEM_TOTAL);
    cudaFuncSetAttribute(k_gemm<JD, 1>,
                         cudaFuncAttributeMaxDynamicSharedMemorySize, SMEM_TOTAL);

    // pack fp16 weights
    k_conv_w<<<2048, 256>>>((const float4*)base_w, (const float4*)lora_A);
    k_conv_bc<<<(NE * DOUT * RL + 255) / 256, 256>>>(lora_B);

    // fp32 gate (exact routing) + fused x -> fp16 conversion
    k_gate<<<TOK / 16, 256>>>(x, gate_w);

    // big GEMM: base output + bias, and low-rank activations (extended N)
    k_gemm<DIN, 0><<<dim3(NEXTN / 128, TOK / 256), 256, SMEM_TOTAL>>>(base_b, out);

    // routed, scaled low-rank activations
    k_z<<<(TOK * JD + 255) / 256, 256>>>();

    // out += z @ Bcat^T
    k_gemm<JD, 1><<<dim3(DOUT / 128, TOK / 256), 256, SMEM_TOTAL>>>(nullptr, out);
}

// round 6
// speedup vs baseline: 1.1082x; 1.0421x over previous
#include <cuda_runtime.h>
#include <cuda_fp16.h>
#include <stdint.h>
#include <stddef.h>

// ---------------------------------------------------------------------------
// Problem constants
// ---------------------------------------------------------------------------
#define TOK   4096          // B*S tokens
#define DIN   4096
#define DOUT  4096
#define NE    8             // experts
#define RL    16            // lora rank
#define JD    128           // NE*RL
#define NEXTN (DOUT + JD)   // 4224 extended N (base cols + lora_A rows)

// ---------------------------------------------------------------------------
// Scratch (static device globals: allocation-free rule)
// ---------------------------------------------------------------------------
static __device__ __half g_xh [(size_t)TOK   * DIN];   // x in fp16
static __device__ __half g_wh [(size_t)NEXTN * DIN];   // [base_w ; lora_A] fp16
static __device__ __half g_bch[(size_t)DOUT  * JD];    // Bcat[o, e*16+r] fp16
static __device__ __half g_zh [(size_t)TOK   * JD];    // z = g*low fp16
static __device__ float  g_low[(size_t)TOK   * JD];    // low-rank activations
static __device__ float  g_gs [(size_t)TOK   * NE];    // routing weights * SCALING

// ---------------------------------------------------------------------------
// PTX helpers
// ---------------------------------------------------------------------------
__device__ __forceinline__ uint32_t smem_u32(const void* p) {
    uint32_t a;
    asm("{ .reg .u64 t; cvta.to.shared.u64 t, %1; cvt.u32.u64 %0, t; }"
        : "=r"(a) : "l"(p));
    return a;
}

__device__ __forceinline__ void ldsm_x4(uint32_t& r0, uint32_t& r1,
                                        uint32_t& r2, uint32_t& r3,
                                        uint32_t addr) {
    asm volatile("ldmatrix.sync.aligned.m8n8.x4.shared.b16 {%0,%1,%2,%3}, [%4];"
                 : "=r"(r0), "=r"(r1), "=r"(r2), "=r"(r3) : "r"(addr));
}

__device__ __forceinline__ void mma16816(float& c0, float& c1, float& c2, float& c3,
                                         uint32_t a0, uint32_t a1, uint32_t a2, uint32_t a3,
                                         uint32_t b0, uint32_t b1) {
    asm volatile(
        "mma.sync.aligned.m16n8k16.row.col.f32.f16.f16.f32 "
        "{%0,%1,%2,%3}, {%4,%5,%6,%7}, {%8,%9}, {%0,%1,%2,%3};"
        : "+f"(c0), "+f"(c1), "+f"(c2), "+f"(c3)
        : "r"(a0), "r"(a1), "r"(a2), "r"(a3), "r"(b0), "r"(b1));
}

#define CP_ASYNC16(smem, gptr)                                         \
    asm volatile("cp.async.cg.shared.global [%0], [%1], 16;"           \
                 :: "r"(smem), "l"(gptr))
#define CP_COMMIT() asm volatile("cp.async.commit_group;" ::: "memory")
#define CP_WAIT1()  asm volatile("cp.async.wait_group 1;" ::: "memory")

// XOR swizzle for 128B rows
__device__ __forceinline__ uint32_t sw128(uint32_t off) {
    return off ^ ((off >> 3) & 0x70);
}

// ---------------------------------------------------------------------------
// Conversion kernels
// ---------------------------------------------------------------------------
__global__ void __launch_bounds__(256) k_conv_w(const float4* __restrict__ bw,
                                                const float4* __restrict__ la) {
    const int n4_base = (DOUT * DIN) / 4;
    const int n4_tot  = (NEXTN * DIN) / 4;
    for (int i = blockIdx.x * blockDim.x + threadIdx.x; i < n4_tot;
         i += gridDim.x * blockDim.x) {
        float4 v = (i < n4_base) ? bw[i] : la[i - n4_base];
        __half2* o = reinterpret_cast<__half2*>(g_wh + (size_t)i * 4);
        o[0] = __floats2half2_rn(v.x, v.y);
        o[1] = __floats2half2_rn(v.z, v.w);
    }
}

// lora_B [E, DOUT, R] -> Bcat [DOUT, JD] with j = e*16 + r
__global__ void __launch_bounds__(256) k_conv_bc(const float* __restrict__ lb) {
    int idx = blockIdx.x * blockDim.x + threadIdx.x;
    if (idx < NE * DOUT * RL) {
        int e = idx >> 16;
        int rem = idx & 0xFFFF;
        int o = rem >> 4;
        int r = rem & 15;
        g_bch[(size_t)o * JD + e * RL + r] = __float2half(lb[idx]);
    }
}

// ---------------------------------------------------------------------------
// Gate (fused with x fp32->fp16 conversion)
// ---------------------------------------------------------------------------
__global__ void __launch_bounds__(256) k_gate(const float* __restrict__ x,
                                              const float* __restrict__ gw) {
    __shared__ float4 sgw[NE * 128];      // 8 x 512 floats = 16 KB
    const int tid = threadIdx.x;
    const int wid = tid >> 5, lane = tid & 31;
    const int t0 = blockIdx.x * 16 + wid * 2;

    float acc[2][NE];
#pragma unroll
    for (int tt = 0; tt < 2; tt++)
#pragma unroll
        for (int e = 0; e < NE; e++) acc[tt][e] = 0.f;

    for (int ch = 0; ch < DIN / 512; ch++) {
#pragma unroll
        for (int i = tid; i < NE * 128; i += 256) {
            int e = i >> 7, c = i & 127;
            sgw[i] = reinterpret_cast<const float4*>(gw + (size_t)e * DIN + ch * 512)[c];
        }
        __syncthreads();
#pragma unroll
        for (int tt = 0; tt < 2; tt++) {
            const float4* xr = reinterpret_cast<const float4*>(
                x + (size_t)(t0 + tt) * DIN + ch * 512);
            __half2* xo = reinterpret_cast<__half2*>(
                g_xh + (size_t)(t0 + tt) * DIN + ch * 512);
#pragma unroll
            for (int j0 = 0; j0 < 4; j0++) {
                int j = lane + j0 * 32;
                float4 v = xr[j];
                xo[2 * j]     = __floats2half2_rn(v.x, v.y);
                xo[2 * j + 1] = __floats2half2_rn(v.z, v.w);
#pragma unroll
                for (int e = 0; e < NE; e++) {
                    float4 w = sgw[e * 128 + j];
                    acc[tt][e] = fmaf(v.x, w.x,
                                 fmaf(v.y, w.y,
                                 fmaf(v.z, w.z,
                                 fmaf(v.w, w.w, acc[tt][e]))));
                }
            }
        }
        __syncthreads();
    }

#pragma unroll
    for (int tt = 0; tt < 2; tt++)
#pragma unroll
        for (int e = 0; e < NE; e++)
            for (int o = 16; o; o >>= 1)
                acc[tt][e] += __shfl_xor_sync(0xffffffffu, acc[tt][e], o);

    if (lane == 0) {
#pragma unroll
        for (int tt = 0; tt < 2; tt++) {
            float* lg = acc[tt];
            int i1 = 0;
            for (int e = 1; e < NE; e++) if (lg[e] > lg[i1]) i1 = e;
            int i2 = (i1 == 0) ? 1 : 0;
            for (int e = 0; e < NE; e++)
                if (e != i1 && lg[e] > lg[i2]) i2 = e;
            float e2 = expf(lg[i2] - lg[i1]);
            float inv = 1.f / (1.f + e2);
            float* o = g_gs + (size_t)(t0 + tt) * NE;
#pragma unroll
            for (int e = 0; e < NE; e++) o[e] = 0.f;
            o[i1] = 2.0f * inv;        // SCALING = 2.0 folded
            o[i2] = 2.0f * e2 * inv;
        }
    }
}

// z[t, j] = gs[t, e(j)] * low[t, j]   (fp16)
__global__ void __launch_bounds__(256) k_z() {
    int i = blockIdx.x * blockDim.x + threadIdx.x;
    if (i < TOK * JD) {
        int t = i >> 7, j = i & 127, e = j >> 4;
        g_zh[i] = __float2half(g_gs[t * NE + e] * g_low[i]);
    }
}

// ---------------------------------------------------------------------------
// mma.sync GEMM: D = A @ B^T, fp16 in / fp32 accum.
//   CTA tile 128(M) x 128(N) x BK64, 256 thr = 2(M)x4(N) warps (64x32/warp),
//   3-stage cp.async pipeline, ONE __syncthreads per K-chunk,
//   96 KB smem -> 2 CTAs/SM (16 warps/SM) for cross-CTA latency hiding.
//     wait_group 1 -> barrier -> issue(kc+2) -> compute(kc)
//   WAR: buffer (kc+2)%3 == (kc-1)%3 was fully read before this barrier.
// ---------------------------------------------------------------------------
#define BK 64
#define NSTAGE 3
#define T_STAGE (128 * BK * 2)   // 16 KB per operand per stage
#define B_OFF   (NSTAGE * T_STAGE)
#define SMEM_TOTAL (2 * NSTAGE * T_STAGE)   // 96 KB

template <int KTOT, int MODE>
__global__ void __launch_bounds__(256, 2)
k_gemm(const float* __restrict__ bias, float* __restrict__ out) {
    extern __shared__ __align__(1024) char smem[];
    const uint32_t sbase = smem_u32(smem);

    const int tid = threadIdx.x;
    const int wid = tid >> 5, lane = tid & 31;
    const int warp_m = wid & 1;              // 2 warps over M (64 rows each)
    const int warp_n = wid >> 1;             // 4 warps over N (32 cols each)

    const __half* Abase = (MODE == 0) ? g_xh : g_zh;
    const __half* Bbase = (MODE == 0) ? g_wh : g_bch;

    const int ld_row = tid >> 3;             // 0..31
    const int ld_chk = tid & 7;              // 0..7
    const __half* gA = Abase + ((size_t)blockIdx.y * 128 + ld_row) * KTOT + ld_chk * 8;
    const __half* gB = Bbase + ((size_t)blockIdx.x * 128 + ld_row) * KTOT + ld_chk * 8;

    uint32_t stOff[4];
#pragma unroll
    for (int p = 0; p < 4; p++)
        stOff[p] = sw128((uint32_t)(ld_row + 32 * p) * 128 + ld_chk * 16);

    const int aRow = warp_m * 64 + (lane & 15);                      // + mi*16
    const int aColH = (lane >> 4) * 8;                               // + ks*16
    const int bRow = warp_n * 32 + (lane & 7) + ((lane >> 4) * 8);   // + ni2*16
    const int bColH = ((lane >> 3) & 1) * 8;                         // + ks*16

    float acc[4][4][4];
#pragma unroll
    for (int mi = 0; mi < 4; mi++)
#pragma unroll
        for (int ni = 0; ni < 4; ni++)
#pragma unroll
            for (int c = 0; c < 4; c++) acc[mi][ni][c] = 0.f;

    const int NK = KTOT / BK;

    auto issue = [&](int kstage) {
        const int st = kstage % NSTAGE;
        const __half* ga = gA + kstage * BK;
        const __half* gb = gB + kstage * BK;
        const uint32_t aBuf = sbase + st * T_STAGE;
        const uint32_t bBuf = sbase + B_OFF + st * T_STAGE;
#pragma unroll
        for (int p = 0; p < 4; p++) {
            CP_ASYNC16(aBuf + stOff[p], ga + (size_t)(32 * p) * KTOT);
            CP_ASYNC16(bBuf + stOff[p], gb + (size_t)(32 * p) * KTOT);
        }
    };

    // prologue: stages 0,1 (NK >= 2 always)
    issue(0); CP_COMMIT();
    issue(1); CP_COMMIT();

    for (int kc = 0; kc < NK; kc++) {
        CP_WAIT1();            // own groups: stage kc written
        __syncthreads();       // all threads' parts visible; WAR protection

        if (kc + 2 < NK) issue(kc + 2);
        CP_COMMIT();           // one group per iteration (possibly empty)

        const uint32_t aT = sbase + (kc % NSTAGE) * T_STAGE;
        const uint32_t bT = sbase + B_OFF + (kc % NSTAGE) * T_STAGE;

#pragma unroll
        for (int ks = 0; ks < BK / 16; ks++) {
            uint32_t af[4][4];
#pragma unroll
            for (int mi = 0; mi < 4; mi++) {
                uint32_t off = (uint32_t)(aRow + mi * 16) * 128 +
                               (uint32_t)(aColH + ks * 16) * 2;
                ldsm_x4(af[mi][0], af[mi][1], af[mi][2], af[mi][3],
                        aT + sw128(off));
            }
            uint32_t bf[2][4];
#pragma unroll
            for (int ni2 = 0; ni2 < 2; ni2++) {
                uint32_t off = (uint32_t)(bRow + ni2 * 16) * 128 +
                               (uint32_t)(bColH + ks * 16) * 2;
                ldsm_x4(bf[ni2][0], bf[ni2][1], bf[ni2][2], bf[ni2][3],
                        bT + sw128(off));
            }
#pragma unroll
            for (int mi = 0; mi < 4; mi++) {
#pragma unroll
                for (int ni = 0; ni < 4; ni++) {
                    uint32_t b0 = bf[ni >> 1][(ni & 1) * 2 + 0];
                    uint32_t b1 = bf[ni >> 1][(ni & 1) * 2 + 1];
                    mma16816(acc[mi][ni][0], acc[mi][ni][1],
                             acc[mi][ni][2], acc[mi][ni][3],
                             af[mi][0], af[mi][1], af[mi][2], af[mi][3],
                             b0, b1);
                }
            }
        }
        // no trailing barrier: next iteration's barrier provides WAR safety
    }

    // ---------------- epilogue ----------------
    const int colCta  = blockIdx.x * 128;
    const int rowBase = blockIdx.y * 128 + warp_m * 64 + (lane >> 2);
    const int colBase = colCta + warp_n * 32 + (lane & 3) * 2;

    if (MODE == 0 && colCta >= DOUT) {
#pragma unroll
        for (int mi = 0; mi < 4; mi++) {
#pragma unroll
            for (int ni = 0; ni < 4; ni++) {
                int r0 = rowBase + mi * 16;
                int c0 = colBase + ni * 8 - DOUT;
                float* o = g_low + (size_t)r0 * JD + c0;
                o[0] = acc[mi][ni][0];
                o[1] = acc[mi][ni][1];
                o += 8 * JD;
                o[0] = acc[mi][ni][2];
                o[1] = acc[mi][ni][3];
            }
        }
    } else {
#pragma unroll
        for (int mi = 0; mi < 4; mi++) {
#pragma unroll
            for (int ni = 0; ni < 4; ni++) {
                int r0 = rowBase + mi * 16;
                int c0 = colBase + ni * 8;
                float* o = out + (size_t)r0 * DOUT + c0;
                if (MODE == 0) {
                    float b0 = __ldg(bias + c0);
                    float b1 = __ldg(bias + c0 + 1);
                    o[0] = acc[mi][ni][0] + b0;
                    o[1] = acc[mi][ni][1] + b1;
                    o += 8 * DOUT;
                    o[0] = acc[mi][ni][2] + b0;
                    o[1] = acc[mi][ni][3] + b1;
                } else {
                    o[0] += acc[mi][ni][0];
                    o[1] += acc[mi][ni][1];
                    o += 8 * DOUT;
                    o[0] += acc[mi][ni][2];
                    o[1] += acc[mi][ni][3];
                }
            }
        }
    }
}

// ---------------------------------------------------------------------------
// Launcher
// ---------------------------------------------------------------------------
extern "C" void kernel_launch(void* const* d_in, const int* in_sizes, int n_in,
                              void* d_out, int out_size) {
    const float* x      = (const float*)d_in[0];
    const float* gate_w = (const float*)d_in[1];
    const float* base_w = (const float*)d_in[2];
    const float* base_b = (const float*)d_in[3];
    const float* lora_A = (const float*)d_in[4];
    const float* lora_B = (const float*)d_in[5];
    float* out = (float*)d_out;

    cudaFuncSetAttribute(k_gemm<DIN, 0>,
                         cudaFuncAttributeMaxDynamicSharedMemorySize, SMEM_TOTAL);
    cudaFuncSetAttribute(k_gemm<JD, 1>,
                         cudaFuncAttributeMaxDynamicSharedMemorySize, SMEM_TOTAL);

    // pack fp16 weights
    k_conv_w<<<2048, 256>>>((const float4*)base_w, (const float4*)lora_A);
    k_conv_bc<<<(NE * DOUT * RL + 255) / 256, 256>>>(lora_B);

    // fp32 gate (exact routing) + fused x -> fp16 conversion
    k_gate<<<TOK / 16, 256>>>(x, gate_w);

    // big GEMM: base output + bias, and low-rank activations (extended N)
    k_gemm<DIN, 0><<<dim3(NEXTN / 128, TOK / 128), 256, SMEM_TOTAL>>>(base_b, out);

    // routed, scaled low-rank activations
    k_z<<<(TOK * JD + 255) / 256, 256>>>();

    // out += z @ Bcat^T
    k_gemm<JD, 1><<<dim3(DOUT / 128, TOK / 128), 256, SMEM_TOTAL>>>(nullptr, out);
}

// round 7
// speedup vs baseline: 1.2996x; 1.1727x over previous
#include <cuda_runtime.h>
#include <cuda_fp16.h>
#include <stdint.h>
#include <stddef.h>

// ---------------------------------------------------------------------------
// Problem constants
// ---------------------------------------------------------------------------
#define TOK   4096          // B*S tokens
#define DIN   4096
#define DOUT  4096
#define NE    8             // experts
#define RL    16            // lora rank
#define JD    128           // NE*RL
#define NEXTN (DOUT + JD)   // 4224 extended N (base cols + lora_A rows)

// ---------------------------------------------------------------------------
// Scratch (static device globals: allocation-free rule)
// ---------------------------------------------------------------------------
static __device__ __half g_xh [(size_t)TOK   * DIN];   // x in fp16
static __device__ __half g_wh [(size_t)NEXTN * DIN];   // [base_w ; lora_A] fp16
static __device__ __half g_bch[(size_t)DOUT  * JD];    // Bcat[o, e*16+r] fp16
static __device__ float  g_low[(size_t)TOK   * JD];    // low-rank activations
static __device__ float  g_gs [(size_t)TOK   * NE];    // routing weights * SCALING

// ---------------------------------------------------------------------------
// PTX helpers
// ---------------------------------------------------------------------------
__device__ __forceinline__ uint32_t smem_u32(const void* p) {
    uint32_t a;
    asm("{ .reg .u64 t; cvta.to.shared.u64 t, %1; cvt.u32.u64 %0, t; }"
        : "=r"(a) : "l"(p));
    return a;
}

__device__ __forceinline__ void ldsm_x4(uint32_t& r0, uint32_t& r1,
                                        uint32_t& r2, uint32_t& r3,
                                        uint32_t addr) {
    asm volatile("ldmatrix.sync.aligned.m8n8.x4.shared.b16 {%0,%1,%2,%3}, [%4];"
                 : "=r"(r0), "=r"(r1), "=r"(r2), "=r"(r3) : "r"(addr));
}

__device__ __forceinline__ void mma16816(float& c0, float& c1, float& c2, float& c3,
                                         uint32_t a0, uint32_t a1, uint32_t a2, uint32_t a3,
                                         uint32_t b0, uint32_t b1) {
    asm volatile(
        "mma.sync.aligned.m16n8k16.row.col.f32.f16.f16.f32 "
        "{%0,%1,%2,%3}, {%4,%5,%6,%7}, {%8,%9}, {%0,%1,%2,%3};"
        : "+f"(c0), "+f"(c1), "+f"(c2), "+f"(c3)
        : "r"(a0), "r"(a1), "r"(a2), "r"(a3), "r"(b0), "r"(b1));
}

#define CP_ASYNC16(smem, gptr)                                         \
    asm volatile("cp.async.cg.shared.global [%0], [%1], 16;"           \
                 :: "r"(smem), "l"(gptr))
#define CP_COMMIT() asm volatile("cp.async.commit_group;" ::: "memory")
#define CP_WAIT1()  asm volatile("cp.async.wait_group 1;" ::: "memory")
#define CP_WAIT0()  asm volatile("cp.async.wait_group 0;" ::: "memory")

// XOR swizzle for 128B rows
__device__ __forceinline__ uint32_t sw128(uint32_t off) {
    return off ^ ((off >> 3) & 0x70);
}

// ---------------------------------------------------------------------------
// k_prep: ONE launch doing gate (+x->fp16), base_w/lora_A->fp16, lora_B pack.
//   blocks [0,256):        gate, 16 tokens each (fused x conversion)
//   blocks [256,2304):     conv_w grid-stride
//   blocks [2304,2368):    conv_bc grid-stride
// ---------------------------------------------------------------------------
#define PREP_GATE_BLKS 256
#define PREP_CONVW_BLKS 2048
#define PREP_GRID (PREP_GATE_BLKS + PREP_CONVW_BLKS + 64)

__global__ void __launch_bounds__(256) k_prep(const float* __restrict__ x,
                                              const float* __restrict__ gw,
                                              const float4* __restrict__ bw,
                                              const float4* __restrict__ la,
                                              const float* __restrict__ lb) {
    __shared__ float4 sgw[NE * 128];      // 16 KB (gate blocks only)
    const int bid = blockIdx.x;
    const int tid = threadIdx.x;

    if (bid < PREP_GATE_BLKS) {
        // ---------------- gate + x conversion ----------------
        const int wid = tid >> 5, lane = tid & 31;
        const int t0 = bid * 16 + wid * 2;

        float acc[2][NE];
#pragma unroll
        for (int tt = 0; tt < 2; tt++)
#pragma unroll
            for (int e = 0; e < NE; e++) acc[tt][e] = 0.f;

        for (int ch = 0; ch < DIN / 512; ch++) {
#pragma unroll
            for (int i = tid; i < NE * 128; i += 256) {
                int e = i >> 7, c = i & 127;
                sgw[i] = reinterpret_cast<const float4*>(
                    gw + (size_t)e * DIN + ch * 512)[c];
            }
            __syncthreads();
#pragma unroll
            for (int tt = 0; tt < 2; tt++) {
                const float4* xr = reinterpret_cast<const float4*>(
                    x + (size_t)(t0 + tt) * DIN + ch * 512);
                __half2* xo = reinterpret_cast<__half2*>(
                    g_xh + (size_t)(t0 + tt) * DIN + ch * 512);
#pragma unroll
                for (int j0 = 0; j0 < 4; j0++) {
                    int j = lane + j0 * 32;
                    float4 v = xr[j];
                    xo[2 * j]     = __floats2half2_rn(v.x, v.y);
                    xo[2 * j + 1] = __floats2half2_rn(v.z, v.w);
#pragma unroll
                    for (int e = 0; e < NE; e++) {
                        float4 w = sgw[e * 128 + j];
                        acc[tt][e] = fmaf(v.x, w.x,
                                     fmaf(v.y, w.y,
                                     fmaf(v.z, w.z,
                                     fmaf(v.w, w.w, acc[tt][e]))));
                    }
                }
            }
            __syncthreads();
        }

#pragma unroll
        for (int tt = 0; tt < 2; tt++)
#pragma unroll
            for (int e = 0; e < NE; e++)
                for (int o = 16; o; o >>= 1)
                    acc[tt][e] += __shfl_xor_sync(0xffffffffu, acc[tt][e], o);

        if (lane == 0) {
#pragma unroll
            for (int tt = 0; tt < 2; tt++) {
                float* lg = acc[tt];
                int i1 = 0;
                for (int e = 1; e < NE; e++) if (lg[e] > lg[i1]) i1 = e;
                int i2 = (i1 == 0) ? 1 : 0;
                for (int e = 0; e < NE; e++)
                    if (e != i1 && lg[e] > lg[i2]) i2 = e;
                float e2 = expf(lg[i2] - lg[i1]);
                float inv = 1.f / (1.f + e2);
                float* o = g_gs + (size_t)(t0 + tt) * NE;
#pragma unroll
                for (int e = 0; e < NE; e++) o[e] = 0.f;
                o[i1] = 2.0f * inv;        // SCALING = 2.0 folded
                o[i2] = 2.0f * e2 * inv;
            }
        }
    } else if (bid < PREP_GATE_BLKS + PREP_CONVW_BLKS) {
        // ---------------- conv_w: [base_w ; lora_A] -> fp16 ----------------
        const int n4_base = (DOUT * DIN) / 4;
        const int n4_tot  = (NEXTN * DIN) / 4;
        for (int i = (bid - PREP_GATE_BLKS) * 256 + tid; i < n4_tot;
             i += PREP_CONVW_BLKS * 256) {
            float4 v = (i < n4_base) ? bw[i] : la[i - n4_base];
            __half2* o = reinterpret_cast<__half2*>(g_wh + (size_t)i * 4);
            o[0] = __floats2half2_rn(v.x, v.y);
            o[1] = __floats2half2_rn(v.z, v.w);
        }
    } else {
        // ---------------- conv_bc: lora_B -> Bcat fp16 ----------------
        for (int idx = (bid - PREP_GATE_BLKS - PREP_CONVW_BLKS) * 256 + tid;
             idx < NE * DOUT * RL; idx += 64 * 256) {
            int e = idx >> 16;
            int rem = idx & 0xFFFF;
            int o = rem >> 4;
            int r = rem & 15;
            g_bch[(size_t)o * JD + e * RL + r] = __float2half(lb[idx]);
        }
    }
}

// ---------------------------------------------------------------------------
// k_gemm1: big GEMM (unchanged from R6): D = A @ B^T, 128x128xBK64 tiles,
//   3-stage cp.async pipeline, one __syncthreads per chunk, 2 CTAs/SM.
//   Epilogue: col<DOUT -> out+bias ; col>=DOUT -> g_low.
// ---------------------------------------------------------------------------
#define BK 64
#define NSTAGE 3
#define T_STAGE (128 * BK * 2)   // 16 KB per operand per stage
#define B_OFF   (NSTAGE * T_STAGE)
#define SMEM_TOTAL (2 * NSTAGE * T_STAGE)   // 96 KB

__global__ void __launch_bounds__(256, 2)
k_gemm1(const float* __restrict__ bias, float* __restrict__ out) {
    extern __shared__ __align__(1024) char smem[];
    const uint32_t sbase = smem_u32(smem);

    const int tid = threadIdx.x;
    const int wid = tid >> 5, lane = tid & 31;
    const int warp_m = wid & 1;
    const int warp_n = wid >> 1;

    const int ld_row = tid >> 3;
    const int ld_chk = tid & 7;
    const __half* gA = g_xh + ((size_t)blockIdx.y * 128 + ld_row) * DIN + ld_chk * 8;
    const __half* gB = g_wh + ((size_t)blockIdx.x * 128 + ld_row) * DIN + ld_chk * 8;

    uint32_t stOff[4];
#pragma unroll
    for (int p = 0; p < 4; p++)
        stOff[p] = sw128((uint32_t)(ld_row + 32 * p) * 128 + ld_chk * 16);

    const int aRow = warp_m * 64 + (lane & 15);
    const int aColH = (lane >> 4) * 8;
    const int bRow = warp_n * 32 + (lane & 7) + ((lane >> 4) * 8);
    const int bColH = ((lane >> 3) & 1) * 8;

    float acc[4][4][4];
#pragma unroll
    for (int mi = 0; mi < 4; mi++)
#pragma unroll
        for (int ni = 0; ni < 4; ni++)
#pragma unroll
            for (int c = 0; c < 4; c++) acc[mi][ni][c] = 0.f;

    const int NK = DIN / BK;

    auto issue = [&](int kstage) {
        const int st = kstage % NSTAGE;
        const __half* ga = gA + kstage * BK;
        const __half* gb = gB + kstage * BK;
        const uint32_t aBuf = sbase + st * T_STAGE;
        const uint32_t bBuf = sbase + B_OFF + st * T_STAGE;
#pragma unroll
        for (int p = 0; p < 4; p++) {
            CP_ASYNC16(aBuf + stOff[p], ga + (size_t)(32 * p) * DIN);
            CP_ASYNC16(bBuf + stOff[p], gb + (size_t)(32 * p) * DIN);
        }
    };

    issue(0); CP_COMMIT();
    issue(1); CP_COMMIT();

    for (int kc = 0; kc < NK; kc++) {
        CP_WAIT1();
        __syncthreads();

        if (kc + 2 < NK) issue(kc + 2);
        CP_COMMIT();

        const uint32_t aT = sbase + (kc % NSTAGE) * T_STAGE;
        const uint32_t bT = sbase + B_OFF + (kc % NSTAGE) * T_STAGE;

#pragma unroll
        for (int ks = 0; ks < BK / 16; ks++) {
            uint32_t af[4][4];
#pragma unroll
            for (int mi = 0; mi < 4; mi++) {
                uint32_t off = (uint32_t)(aRow + mi * 16) * 128 +
                               (uint32_t)(aColH + ks * 16) * 2;
                ldsm_x4(af[mi][0], af[mi][1], af[mi][2], af[mi][3],
                        aT + sw128(off));
            }
            uint32_t bf[2][4];
#pragma unroll
            for (int ni2 = 0; ni2 < 2; ni2++) {
                uint32_t off = (uint32_t)(bRow + ni2 * 16) * 128 +
                               (uint32_t)(bColH + ks * 16) * 2;
                ldsm_x4(bf[ni2][0], bf[ni2][1], bf[ni2][2], bf[ni2][3],
                        bT + sw128(off));
            }
#pragma unroll
            for (int mi = 0; mi < 4; mi++) {
#pragma unroll
                for (int ni = 0; ni < 4; ni++) {
                    uint32_t b0 = bf[ni >> 1][(ni & 1) * 2 + 0];
                    uint32_t b1 = bf[ni >> 1][(ni & 1) * 2 + 1];
                    mma16816(acc[mi][ni][0], acc[mi][ni][1],
                             acc[mi][ni][2], acc[mi][ni][3],
                             af[mi][0], af[mi][1], af[mi][2], af[mi][3],
                             b0, b1);
                }
            }
        }
    }

    const int colCta  = blockIdx.x * 128;
    const int rowBase = blockIdx.y * 128 + warp_m * 64 + (lane >> 2);
    const int colBase = colCta + warp_n * 32 + (lane & 3) * 2;

    if (colCta >= DOUT) {
#pragma unroll
        for (int mi = 0; mi < 4; mi++) {
#pragma unroll
            for (int ni = 0; ni < 4; ni++) {
                int r0 = rowBase + mi * 16;
                int c0 = colBase + ni * 8 - DOUT;
                float* o = g_low + (size_t)r0 * JD + c0;
                o[0] = acc[mi][ni][0];
                o[1] = acc[mi][ni][1];
                o += 8 * JD;
                o[0] = acc[mi][ni][2];
                o[1] = acc[mi][ni][3];
            }
        }
    } else {
#pragma unroll
        for (int mi = 0; mi < 4; mi++) {
#pragma unroll
            for (int ni = 0; ni < 4; ni++) {
                int r0 = rowBase + mi * 16;
                int c0 = colBase + ni * 8;
                float* o = out + (size_t)r0 * DOUT + c0;
                float b0 = __ldg(bias + c0);
                float b1 = __ldg(bias + c0 + 1);
                o[0] = acc[mi][ni][0] + b0;
                o[1] = acc[mi][ni][1] + b1;
                o += 8 * DOUT;
                o[0] = acc[mi][ni][2] + b0;
                o[1] = acc[mi][ni][3] + b1;
            }
        }
    }
}

// ---------------------------------------------------------------------------
// k_gemm2: out += z @ Bcat^T, with z = gs*low computed INLINE into smem.
//   K = JD = 128 fits entirely in smem: A (fp16, from g_low*g_gs) built by
//   generic stores, B via cp.async, ONE __syncthreads, 8 mma steps, RMW out.
//   smem: A 32 KB + B 32 KB = 64 KB.
// ---------------------------------------------------------------------------
#define G2_SMEM (4 * T_STAGE)   // 64 KB

__global__ void __launch_bounds__(256, 2)
k_gemm2(float* __restrict__ out) {
    extern __shared__ __align__(1024) char smem[];
    const uint32_t sbase = smem_u32(smem);
    const uint32_t bBase = sbase + 2 * T_STAGE;

    const int tid = threadIdx.x;
    const int wid = tid >> 5, lane = tid & 31;
    const int warp_m = wid & 1;
    const int warp_n = wid >> 1;

    // B loads (K=128 = 2 chunks of 64 cols)
    const int ld_row = tid >> 3;
    const int ld_chk = tid & 7;
    const __half* gB = g_bch + ((size_t)blockIdx.x * 128 + ld_row) * JD + ld_chk * 8;
    uint32_t stOff[4];
#pragma unroll
    for (int p = 0; p < 4; p++)
        stOff[p] = sw128((uint32_t)(ld_row + 32 * p) * 128 + ld_chk * 16);

#pragma unroll
    for (int kc = 0; kc < 2; kc++) {
#pragma unroll
        for (int p = 0; p < 4; p++)
            CP_ASYNC16(bBase + kc * T_STAGE + stOff[p],
                       gB + kc * 64 + (size_t)(32 * p) * JD);
    }
    CP_COMMIT();

    // A = fp16(gs * low), built directly in swizzled smem.
    // 128 rows x 64 half2 cols; thread i handles strided half2 elements.
    {
        const int rowG = blockIdx.y * 128;
#pragma unroll
        for (int i = tid; i < 128 * 64; i += 256) {
            int row = i >> 6;
            int jc = i & 63;          // half2 column
            int j = jc * 2;
            int grow = rowG + row;
            float g = g_gs[(size_t)grow * NE + (j >> 4)];
            const float* lp = g_low + (size_t)grow * JD + j;
            __half2 v = __floats2half2_rn(g * lp[0], g * lp[1]);
            int kc = j >> 6;          // which 64-col chunk
            uint32_t off = (uint32_t)row * 128 + (uint32_t)(j & 63) * 2;
            *reinterpret_cast<__half2*>(smem + kc * T_STAGE + sw128(off)) = v;
        }
    }

    CP_WAIT0();
    __syncthreads();

    const int aRow = warp_m * 64 + (lane & 15);
    const int aColH = (lane >> 4) * 8;
    const int bRow = warp_n * 32 + (lane & 7) + ((lane >> 4) * 8);
    const int bColH = ((lane >> 3) & 1) * 8;

    float acc[4][4][4];
#pragma unroll
    for (int mi = 0; mi < 4; mi++)
#pragma unroll
        for (int ni = 0; ni < 4; ni++)
#pragma unroll
            for (int c = 0; c < 4; c++) acc[mi][ni][c] = 0.f;

#pragma unroll
    for (int kc = 0; kc < 2; kc++) {
        const uint32_t aT = sbase + kc * T_STAGE;
        const uint32_t bT = bBase + kc * T_STAGE;
#pragma unroll
        for (int ks = 0; ks < 4; ks++) {
            uint32_t af[4][4];
#pragma unroll
            for (int mi = 0; mi < 4; mi++) {
                uint32_t off = (uint32_t)(aRow + mi * 16) * 128 +
                               (uint32_t)(aColH + ks * 16) * 2;
                ldsm_x4(af[mi][0], af[mi][1], af[mi][2], af[mi][3],
                        aT + sw128(off));
            }
            uint32_t bf[2][4];
#pragma unroll
            for (int ni2 = 0; ni2 < 2; ni2++) {
                uint32_t off = (uint32_t)(bRow + ni2 * 16) * 128 +
                               (uint32_t)(bColH + ks * 16) * 2;
                ldsm_x4(bf[ni2][0], bf[ni2][1], bf[ni2][2], bf[ni2][3],
                        bT + sw128(off));
            }
#pragma unroll
            for (int mi = 0; mi < 4; mi++) {
#pragma unroll
                for (int ni = 0; ni < 4; ni++) {
                    uint32_t b0 = bf[ni >> 1][(ni & 1) * 2 + 0];
                    uint32_t b1 = bf[ni >> 1][(ni & 1) * 2 + 1];
                    mma16816(acc[mi][ni][0], acc[mi][ni][1],
                             acc[mi][ni][2], acc[mi][ni][3],
                             af[mi][0], af[mi][1], af[mi][2], af[mi][3],
                             b0, b1);
                }
            }
        }
    }

    const int rowBase = blockIdx.y * 128 + warp_m * 64 + (lane >> 2);
    const int colBase = blockIdx.x * 128 + warp_n * 32 + (lane & 3) * 2;
#pragma unroll
    for (int mi = 0; mi < 4; mi++) {
#pragma unroll
        for (int ni = 0; ni < 4; ni++) {
            int r0 = rowBase + mi * 16;
            int c0 = colBase + ni * 8;
            float* o = out + (size_t)r0 * DOUT + c0;
            o[0] += acc[mi][ni][0];
            o[1] += acc[mi][ni][1];
            o += 8 * DOUT;
            o[0] += acc[mi][ni][2];
            o[1] += acc[mi][ni][3];
        }
    }
}

// ---------------------------------------------------------------------------
// Launcher
// ---------------------------------------------------------------------------
extern "C" void kernel_launch(void* const* d_in, const int* in_sizes, int n_in,
                              void* d_out, int out_size) {
    const float* x      = (const float*)d_in[0];
    const float* gate_w = (const float*)d_in[1];
    const float* base_w = (const float*)d_in[2];
    const float* base_b = (const float*)d_in[3];
    const float* lora_A = (const float*)d_in[4];
    const float* lora_B = (const float*)d_in[5];
    float* out = (float*)d_out;

    cudaFuncSetAttribute(k_gemm1,
                         cudaFuncAttributeMaxDynamicSharedMemorySize, SMEM_TOTAL);
    cudaFuncSetAttribute(k_gemm2,
                         cudaFuncAttributeMaxDynamicSharedMemorySize, G2_SMEM);

    // one prep launch: gate (+x conversion) | weight conversion | Bcat pack
    k_prep<<<PREP_GRID, 256>>>(x, gate_w, (const float4*)base_w,
                               (const float4*)lora_A, lora_B);

    // big GEMM: base output + bias, and low-rank activations (extended N)
    k_gemm1<<<dim3(NEXTN / 128, TOK / 128), 256, SMEM_TOTAL>>>(base_b, out);

    // out += (gs*low) @ Bcat^T  (z computed inline)
    k_gemm2<<<dim3(DOUT / 128, TOK / 128), 256, G2_SMEM>>>(out);
}

// round 8
// speedup vs baseline: 1.3989x; 1.0764x over previous
#include <cuda_runtime.h>
#include <cuda_fp16.h>
#include <stdint.h>
#include <stddef.h>

// ---------------------------------------------------------------------------
// Problem constants
// ---------------------------------------------------------------------------
#define TOK   4096          // B*S tokens
#define DIN   4096
#define DOUT  4096
#define NE    8             // experts
#define RL    16            // lora rank
#define JD    128           // NE*RL
#define NSPLIT 8            // K-splits for k_low

// ---------------------------------------------------------------------------
// Scratch (static device globals: allocation-free rule)
// ---------------------------------------------------------------------------
static __device__ __half g_xh  [(size_t)TOK  * DIN];   // x fp16
static __device__ __half g_wh  [(size_t)DOUT * DIN];   // base_w fp16
static __device__ __half g_lah [(size_t)JD   * DIN];   // lora_A fp16
static __device__ __half g_bch [(size_t)DOUT * JD];    // Bcat[o, e*16+r] fp16
static __device__ __half g_zh  [(size_t)TOK  * JD];    // z = gs*low fp16
static __device__ float  g_lowp[NSPLIT][(size_t)TOK * JD]; // split-K partials
static __device__ float  g_gs  [(size_t)TOK  * NE];    // routing weights * SCALING

// ---------------------------------------------------------------------------
// PTX helpers
// ---------------------------------------------------------------------------
__device__ __forceinline__ uint32_t smem_u32(const void* p) {
    uint32_t a;
    asm("{ .reg .u64 t; cvta.to.shared.u64 t, %1; cvt.u32.u64 %0, t; }"
        : "=r"(a) : "l"(p));
    return a;
}

__device__ __forceinline__ void ldsm_x4(uint32_t& r0, uint32_t& r1,
                                        uint32_t& r2, uint32_t& r3,
                                        uint32_t addr) {
    asm volatile("ldmatrix.sync.aligned.m8n8.x4.shared.b16 {%0,%1,%2,%3}, [%4];"
                 : "=r"(r0), "=r"(r1), "=r"(r2), "=r"(r3) : "r"(addr));
}

__device__ __forceinline__ void mma16816(float& c0, float& c1, float& c2, float& c3,
                                         uint32_t a0, uint32_t a1, uint32_t a2, uint32_t a3,
                                         uint32_t b0, uint32_t b1) {
    asm volatile(
        "mma.sync.aligned.m16n8k16.row.col.f32.f16.f16.f32 "
        "{%0,%1,%2,%3}, {%4,%5,%6,%7}, {%8,%9}, {%0,%1,%2,%3};"
        : "+f"(c0), "+f"(c1), "+f"(c2), "+f"(c3)
        : "r"(a0), "r"(a1), "r"(a2), "r"(a3), "r"(b0), "r"(b1));
}

#define CP_ASYNC16(smem, gptr)                                         \
    asm volatile("cp.async.cg.shared.global [%0], [%1], 16;"           \
                 :: "r"(smem), "l"(gptr))
#define CP_COMMIT() asm volatile("cp.async.commit_group;" ::: "memory")
#define CP_WAIT1()  asm volatile("cp.async.wait_group 1;" ::: "memory")
#define CP_WAIT0()  asm volatile("cp.async.wait_group 0;" ::: "memory")

__device__ __forceinline__ uint32_t sw128(uint32_t off) {
    return off ^ ((off >> 3) & 0x70);
}

// ---------------------------------------------------------------------------
// k_prep: gate (+x->fp16) | base_w->fp16 | lora_A->fp16 | lora_B pack
// ---------------------------------------------------------------------------
#define PREP_GATE_BLKS 256
#define PREP_CONVW_BLKS 2048
#define PREP_GRID (PREP_GATE_BLKS + PREP_CONVW_BLKS + 64)

__global__ void __launch_bounds__(256) k_prep(const float* __restrict__ x,
                                              const float* __restrict__ gw,
                                              const float4* __restrict__ bw,
                                              const float4* __restrict__ la,
                                              const float* __restrict__ lb) {
    __shared__ float4 sgw[NE * 128];      // 16 KB (gate blocks only)
    const int bid = blockIdx.x;
    const int tid = threadIdx.x;

    if (bid < PREP_GATE_BLKS) {
        // ---------------- gate + x conversion ----------------
        const int wid = tid >> 5, lane = tid & 31;
        const int t0 = bid * 16 + wid * 2;

        float acc[2][NE];
#pragma unroll
        for (int tt = 0; tt < 2; tt++)
#pragma unroll
            for (int e = 0; e < NE; e++) acc[tt][e] = 0.f;

        for (int ch = 0; ch < DIN / 512; ch++) {
#pragma unroll
            for (int i = tid; i < NE * 128; i += 256) {
                int e = i >> 7, c = i & 127;
                sgw[i] = reinterpret_cast<const float4*>(
                    gw + (size_t)e * DIN + ch * 512)[c];
            }
            __syncthreads();
#pragma unroll
            for (int tt = 0; tt < 2; tt++) {
                const float4* xr = reinterpret_cast<const float4*>(
                    x + (size_t)(t0 + tt) * DIN + ch * 512);
                __half2* xo = reinterpret_cast<__half2*>(
                    g_xh + (size_t)(t0 + tt) * DIN + ch * 512);
#pragma unroll
                for (int j0 = 0; j0 < 4; j0++) {
                    int j = lane + j0 * 32;
                    float4 v = xr[j];
                    xo[2 * j]     = __floats2half2_rn(v.x, v.y);
                    xo[2 * j + 1] = __floats2half2_rn(v.z, v.w);
#pragma unroll
                    for (int e = 0; e < NE; e++) {
                        float4 w = sgw[e * 128 + j];
                        acc[tt][e] = fmaf(v.x, w.x,
                                     fmaf(v.y, w.y,
                                     fmaf(v.z, w.z,
                                     fmaf(v.w, w.w, acc[tt][e]))));
                    }
                }
            }
            __syncthreads();
        }

#pragma unroll
        for (int tt = 0; tt < 2; tt++)
#pragma unroll
            for (int e = 0; e < NE; e++)
                for (int o = 16; o; o >>= 1)
                    acc[tt][e] += __shfl_xor_sync(0xffffffffu, acc[tt][e], o);

        if (lane == 0) {
#pragma unroll
            for (int tt = 0; tt < 2; tt++) {
                float* lg = acc[tt];
                int i1 = 0;
                for (int e = 1; e < NE; e++) if (lg[e] > lg[i1]) i1 = e;
                int i2 = (i1 == 0) ? 1 : 0;
                for (int e = 0; e < NE; e++)
                    if (e != i1 && lg[e] > lg[i2]) i2 = e;
                float e2 = expf(lg[i2] - lg[i1]);
                float inv = 1.f / (1.f + e2);
                float* o = g_gs + (size_t)(t0 + tt) * NE;
#pragma unroll
                for (int e = 0; e < NE; e++) o[e] = 0.f;
                o[i1] = 2.0f * inv;        // SCALING = 2.0 folded
                o[i2] = 2.0f * e2 * inv;
            }
        }
    } else if (bid < PREP_GATE_BLKS + PREP_CONVW_BLKS) {
        // ------- conv: base_w -> g_wh ; lora_A -> g_lah -------
        const int n4_base = (DOUT * DIN) / 4;
        const int n4_tot  = n4_base + (JD * DIN) / 4;
        for (int i = (bid - PREP_GATE_BLKS) * 256 + tid; i < n4_tot;
             i += PREP_CONVW_BLKS * 256) {
            if (i < n4_base) {
                float4 v = bw[i];
                __half2* o = reinterpret_cast<__half2*>(g_wh + (size_t)i * 4);
                o[0] = __floats2half2_rn(v.x, v.y);
                o[1] = __floats2half2_rn(v.z, v.w);
            } else {
                float4 v = la[i - n4_base];
                __half2* o = reinterpret_cast<__half2*>(
                    g_lah + (size_t)(i - n4_base) * 4);
                o[0] = __floats2half2_rn(v.x, v.y);
                o[1] = __floats2half2_rn(v.z, v.w);
            }
        }
    } else {
        // ---------------- conv_bc: lora_B -> Bcat fp16 ----------------
        for (int idx = (bid - PREP_GATE_BLKS - PREP_CONVW_BLKS) * 256 + tid;
             idx < NE * DOUT * RL; idx += 64 * 256) {
            int e = idx >> 16;
            int rem = idx & 0xFFFF;
            int o = rem >> 4;
            int r = rem & 15;
            g_bch[(size_t)o * JD + e * RL + r] = __float2half(lb[idx]);
        }
    }
}

// ---------------------------------------------------------------------------
// Shared GEMM tile machinery constants
// ---------------------------------------------------------------------------
#define BK 64
#define NSTAGE 3
#define T_STAGE (128 * BK * 2)   // 16 KB per operand per stage
#define B_OFF   (NSTAGE * T_STAGE)
#define SMEM_TOTAL (2 * NSTAGE * T_STAGE)   // 96 KB

// ---------------------------------------------------------------------------
// k_low: split-K GEMM  low_partial[s] = x[., s*512..] @ lora_A[., s*512..]^T
//   grid (NSPLIT, TOK/128); tile 128(M) x 128(N=JD) x K=512.
// ---------------------------------------------------------------------------
__global__ void __launch_bounds__(256, 2)
k_low() {
    extern __shared__ __align__(1024) char smem[];
    const uint32_t sbase = smem_u32(smem);

    const int tid = threadIdx.x;
    const int wid = tid >> 5, lane = tid & 31;
    const int warp_m = wid & 1;
    const int warp_n = wid >> 1;
    const int split = blockIdx.x;

    const int ld_row = tid >> 3;
    const int ld_chk = tid & 7;
    const __half* gA = g_xh + ((size_t)blockIdx.y * 128 + ld_row) * DIN +
                       split * (DIN / NSPLIT) + ld_chk * 8;
    const __half* gB = g_lah + (size_t)ld_row * DIN +
                       split * (DIN / NSPLIT) + ld_chk * 8;

    uint32_t stOff[4];
#pragma unroll
    for (int p = 0; p < 4; p++)
        stOff[p] = sw128((uint32_t)(ld_row + 32 * p) * 128 + ld_chk * 16);

    const int aRow = warp_m * 64 + (lane & 15);
    const int aColH = (lane >> 4) * 8;
    const int bRow = warp_n * 32 + (lane & 7) + ((lane >> 4) * 8);
    const int bColH = ((lane >> 3) & 1) * 8;

    float acc[4][4][4];
#pragma unroll
    for (int mi = 0; mi < 4; mi++)
#pragma unroll
        for (int ni = 0; ni < 4; ni++)
#pragma unroll
            for (int c = 0; c < 4; c++) acc[mi][ni][c] = 0.f;

    const int NK = (DIN / NSPLIT) / BK;   // 8

    auto issue = [&](int kstage) {
        const int st = kstage % NSTAGE;
        const __half* ga = gA + kstage * BK;
        const __half* gb = gB + kstage * BK;
        const uint32_t aBuf = sbase + st * T_STAGE;
        const uint32_t bBuf = sbase + B_OFF + st * T_STAGE;
#pragma unroll
        for (int p = 0; p < 4; p++) {
            CP_ASYNC16(aBuf + stOff[p], ga + (size_t)(32 * p) * DIN);
            CP_ASYNC16(bBuf + stOff[p], gb + (size_t)(32 * p) * DIN);
        }
    };

    issue(0); CP_COMMIT();
    issue(1); CP_COMMIT();

    for (int kc = 0; kc < NK; kc++) {
        CP_WAIT1();
        __syncthreads();
        if (kc + 2 < NK) issue(kc + 2);
        CP_COMMIT();

        const uint32_t aT = sbase + (kc % NSTAGE) * T_STAGE;
        const uint32_t bT = sbase + B_OFF + (kc % NSTAGE) * T_STAGE;

#pragma unroll
        for (int ks = 0; ks < BK / 16; ks++) {
            uint32_t af[4][4];
#pragma unroll
            for (int mi = 0; mi < 4; mi++) {
                uint32_t off = (uint32_t)(aRow + mi * 16) * 128 +
                               (uint32_t)(aColH + ks * 16) * 2;
                ldsm_x4(af[mi][0], af[mi][1], af[mi][2], af[mi][3],
                        aT + sw128(off));
            }
            uint32_t bf[2][4];
#pragma unroll
            for (int ni2 = 0; ni2 < 2; ni2++) {
                uint32_t off = (uint32_t)(bRow + ni2 * 16) * 128 +
                               (uint32_t)(bColH + ks * 16) * 2;
                ldsm_x4(bf[ni2][0], bf[ni2][1], bf[ni2][2], bf[ni2][3],
                        bT + sw128(off));
            }
#pragma unroll
            for (int mi = 0; mi < 4; mi++) {
#pragma unroll
                for (int ni = 0; ni < 4; ni++) {
                    uint32_t b0 = bf[ni >> 1][(ni & 1) * 2 + 0];
                    uint32_t b1 = bf[ni >> 1][(ni & 1) * 2 + 1];
                    mma16816(acc[mi][ni][0], acc[mi][ni][1],
                             acc[mi][ni][2], acc[mi][ni][3],
                             af[mi][0], af[mi][1], af[mi][2], af[mi][3],
                             b0, b1);
                }
            }
        }
    }

    float* outp = g_lowp[split];
    const int rowBase = blockIdx.y * 128 + warp_m * 64 + (lane >> 2);
    const int colBase = warp_n * 32 + (lane & 3) * 2;
#pragma unroll
    for (int mi = 0; mi < 4; mi++) {
#pragma unroll
        for (int ni = 0; ni < 4; ni++) {
            int r0 = rowBase + mi * 16;
            int c0 = colBase + ni * 8;
            float* o = outp + (size_t)r0 * JD + c0;
            o[0] = acc[mi][ni][0];
            o[1] = acc[mi][ni][1];
            o += 8 * JD;
            o[0] = acc[mi][ni][2];
            o[1] = acc[mi][ni][3];
        }
    }
}

// ---------------------------------------------------------------------------
// k_z: z[t,j] = gs[t, e(j)] * sum_s lowp[s][t,j]  -> fp16
//   one half2 (2 adjacent j, same expert) per thread
// ---------------------------------------------------------------------------
__global__ void __launch_bounds__(256) k_z() {
    int i = blockIdx.x * blockDim.x + threadIdx.x;   // half2 index
    if (i < TOK * JD / 2) {
        int t = i >> 6;
        int j = (i & 63) * 2;
        float s0 = 0.f, s1 = 0.f;
#pragma unroll
        for (int s = 0; s < NSPLIT; s++) {
            const float* p = g_lowp[s] + (size_t)t * JD + j;
            s0 += p[0];
            s1 += p[1];
        }
        float g = g_gs[(size_t)t * NE + (j >> 4)];
        reinterpret_cast<__half2*>(g_zh)[i] = __floats2half2_rn(g * s0, g * s1);
    }
}

// ---------------------------------------------------------------------------
// k_gemm1: out = x @ base_w^T + bias + z @ Bcat^T
//   Mainloop identical to R6/R7 (128x128xBK64, 3-stage, one barrier/chunk).
//   TAIL: reuse stage buffers to load z tile + Bcat tile (K=JD=128) and run
//   8 more mma steps into the same accumulators. Single non-RMW epilogue.
// ---------------------------------------------------------------------------
__global__ void __launch_bounds__(256, 2)
k_gemm1(const float* __restrict__ bias, float* __restrict__ out) {
    extern __shared__ __align__(1024) char smem[];
    const uint32_t sbase = smem_u32(smem);

    const int tid = threadIdx.x;
    const int wid = tid >> 5, lane = tid & 31;
    const int warp_m = wid & 1;
    const int warp_n = wid >> 1;

    const int ld_row = tid >> 3;
    const int ld_chk = tid & 7;
    const __half* gA = g_xh + ((size_t)blockIdx.y * 128 + ld_row) * DIN + ld_chk * 8;
    const __half* gB = g_wh + ((size_t)blockIdx.x * 128 + ld_row) * DIN + ld_chk * 8;

    uint32_t stOff[4];
#pragma unroll
    for (int p = 0; p < 4; p++)
        stOff[p] = sw128((uint32_t)(ld_row + 32 * p) * 128 + ld_chk * 16);

    const int aRow = warp_m * 64 + (lane & 15);
    const int aColH = (lane >> 4) * 8;
    const int bRow = warp_n * 32 + (lane & 7) + ((lane >> 4) * 8);
    const int bColH = ((lane >> 3) & 1) * 8;

    float acc[4][4][4];
#pragma unroll
    for (int mi = 0; mi < 4; mi++)
#pragma unroll
        for (int ni = 0; ni < 4; ni++)
#pragma unroll
            for (int c = 0; c < 4; c++) acc[mi][ni][c] = 0.f;

    const int NK = DIN / BK;

    auto issue = [&](int kstage) {
        const int st = kstage % NSTAGE;
        const __half* ga = gA + kstage * BK;
        const __half* gb = gB + kstage * BK;
        const uint32_t aBuf = sbase + st * T_STAGE;
        const uint32_t bBuf = sbase + B_OFF + st * T_STAGE;
#pragma unroll
        for (int p = 0; p < 4; p++) {
            CP_ASYNC16(aBuf + stOff[p], ga + (size_t)(32 * p) * DIN);
            CP_ASYNC16(bBuf + stOff[p], gb + (size_t)(32 * p) * DIN);
        }
    };

    issue(0); CP_COMMIT();
    issue(1); CP_COMMIT();

    for (int kc = 0; kc < NK; kc++) {
        CP_WAIT1();
        __syncthreads();
        if (kc + 2 < NK) issue(kc + 2);
        CP_COMMIT();

        const uint32_t aT = sbase + (kc % NSTAGE) * T_STAGE;
        const uint32_t bT = sbase + B_OFF + (kc % NSTAGE) * T_STAGE;

#pragma unroll
        for (int ks = 0; ks < BK / 16; ks++) {
            uint32_t af[4][4];
#pragma unroll
            for (int mi = 0; mi < 4; mi++) {
                uint32_t off = (uint32_t)(aRow + mi * 16) * 128 +
                               (uint32_t)(aColH + ks * 16) * 2;
                ldsm_x4(af[mi][0], af[mi][1], af[mi][2], af[mi][3],
                        aT + sw128(off));
            }
            uint32_t bf[2][4];
#pragma unroll
            for (int ni2 = 0; ni2 < 2; ni2++) {
                uint32_t off = (uint32_t)(bRow + ni2 * 16) * 128 +
                               (uint32_t)(bColH + ks * 16) * 2;
                ldsm_x4(bf[ni2][0], bf[ni2][1], bf[ni2][2], bf[ni2][3],
                        bT + sw128(off));
            }
#pragma unroll
            for (int mi = 0; mi < 4; mi++) {
#pragma unroll
                for (int ni = 0; ni < 4; ni++) {
                    uint32_t b0 = bf[ni >> 1][(ni & 1) * 2 + 0];
                    uint32_t b1 = bf[ni >> 1][(ni & 1) * 2 + 1];
                    mma16816(acc[mi][ni][0], acc[mi][ni][1],
                             acc[mi][ni][2], acc[mi][ni][3],
                             af[mi][0], af[mi][1], af[mi][2], af[mi][3],
                             b0, b1);
                }
            }
        }
    }

    // ---------------- LoRA tail: acc += z @ Bcat^T (K = JD = 128) ----------
    __syncthreads();   // all warps done reading stage buffers
    {
        const __half* gZ = g_zh + ((size_t)blockIdx.y * 128 + ld_row) * JD + ld_chk * 8;
        const __half* gC = g_bch + ((size_t)blockIdx.x * 128 + ld_row) * JD + ld_chk * 8;
#pragma unroll
        for (int kc = 0; kc < 2; kc++) {
#pragma unroll
            for (int p = 0; p < 4; p++) {
                CP_ASYNC16(sbase + kc * T_STAGE + stOff[p],
                           gZ + kc * 64 + (size_t)(32 * p) * JD);
                CP_ASYNC16(sbase + B_OFF + kc * T_STAGE + stOff[p],
                           gC + kc * 64 + (size_t)(32 * p) * JD);
            }
        }
        CP_COMMIT();
        CP_WAIT0();
        __syncthreads();

#pragma unroll
        for (int kc = 0; kc < 2; kc++) {
            const uint32_t aT = sbase + kc * T_STAGE;
            const uint32_t bT = sbase + B_OFF + kc * T_STAGE;
#pragma unroll
            for (int ks = 0; ks < 4; ks++) {
                uint32_t af[4][4];
#pragma unroll
                for (int mi = 0; mi < 4; mi++) {
                    uint32_t off = (uint32_t)(aRow + mi * 16) * 128 +
                                   (uint32_t)(aColH + ks * 16) * 2;
                    ldsm_x4(af[mi][0], af[mi][1], af[mi][2], af[mi][3],
                            aT + sw128(off));
                }
                uint32_t bf[2][4];
#pragma unroll
                for (int ni2 = 0; ni2 < 2; ni2++) {
                    uint32_t off = (uint32_t)(bRow + ni2 * 16) * 128 +
                                   (uint32_t)(bColH + ks * 16) * 2;
                    ldsm_x4(bf[ni2][0], bf[ni2][1], bf[ni2][2], bf[ni2][3],
                            bT + sw128(off));
                }
#pragma unroll
                for (int mi = 0; mi < 4; mi++) {
#pragma unroll
                    for (int ni = 0; ni < 4; ni++) {
                        uint32_t b0 = bf[ni >> 1][(ni & 1) * 2 + 0];
                        uint32_t b1 = bf[ni >> 1][(ni & 1) * 2 + 1];
                        mma16816(acc[mi][ni][0], acc[mi][ni][1],
                                 acc[mi][ni][2], acc[mi][ni][3],
                                 af[mi][0], af[mi][1], af[mi][2], af[mi][3],
                                 b0, b1);
                    }
                }
            }
        }
    }

    // ---------------- epilogue: out = acc + bias (no RMW) ----------------
    const int rowBase = blockIdx.y * 128 + warp_m * 64 + (lane >> 2);
    const int colBase = blockIdx.x * 128 + warp_n * 32 + (lane & 3) * 2;
#pragma unroll
    for (int mi = 0; mi < 4; mi++) {
#pragma unroll
        for (int ni = 0; ni < 4; ni++) {
            int r0 = rowBase + mi * 16;
            int c0 = colBase + ni * 8;
            float* o = out + (size_t)r0 * DOUT + c0;
            float b0 = __ldg(bias + c0);
            float b1 = __ldg(bias + c0 + 1);
            o[0] = acc[mi][ni][0] + b0;
            o[1] = acc[mi][ni][1] + b1;
            o += 8 * DOUT;
            o[0] = acc[mi][ni][2] + b0;
            o[1] = acc[mi][ni][3] + b1;
        }
    }
}

// ---------------------------------------------------------------------------
// Launcher
// ---------------------------------------------------------------------------
extern "C" void kernel_launch(void* const* d_in, const int* in_sizes, int n_in,
                              void* d_out, int out_size) {
    const float* x      = (const float*)d_in[0];
    const float* gate_w = (const float*)d_in[1];
    const float* base_w = (const float*)d_in[2];
    const float* base_b = (const float*)d_in[3];
    const float* lora_A = (const float*)d_in[4];
    const float* lora_B = (const float*)d_in[5];
    float* out = (float*)d_out;

    cudaFuncSetAttribute(k_low,
                         cudaFuncAttributeMaxDynamicSharedMemorySize, SMEM_TOTAL);
    cudaFuncSetAttribute(k_gemm1,
                         cudaFuncAttributeMaxDynamicSharedMemorySize, SMEM_TOTAL);

    // 1. prep: gate (+x conversion) | base_w/lora_A conversion | Bcat pack
    k_prep<<<PREP_GRID, 256>>>(x, gate_w, (const float4*)base_w,
                               (const float4*)lora_A, lora_B);

    // 2. low-rank activations, split-K partials
    k_low<<<dim3(NSPLIT, TOK / 128), 256, SMEM_TOTAL>>>();

    // 3. reduce partials, apply routing weights, emit fp16 z
    k_z<<<(TOK * JD / 2 + 255) / 256, 256>>>();

    // 4. fused: out = x@W^T + bias + z@Bcat^T
    k_gemm1<<<dim3(DOUT / 128, TOK / 128), 256, SMEM_TOTAL>>>(base_b, out);
}